// round 9
// baseline (speedup 1.0000x reference)
#include <cuda_runtime.h>
#include <cuda_fp16.h>
#include <math.h>
#include <stdint.h>

#define BB 32
#define TT 1500
#define HH 768
#define HM1 767
#define LQ 400
#define MM (BB*LQ)                 /* 12800 */
#define FC_OFF ((size_t)MM*HH)
#define NHAT_OFF ((size_t)2*MM*HH)
#define P_MIX_C 0.15f

// ---------------- scratch (__device__ globals, no allocs) ------------------
__device__ float g_scale[BB];
__device__ float g_nhat_part[BB];
__device__ __half g_sa[(size_t)MM * HH];
__device__ __half g_y1[(size_t)MM * HH];
__device__ __half g_w1t[(size_t)HH * HH];
__device__ __half g_w2t[(size_t)HH * HH];

// ---------------- helpers --------------------------------------------------
__device__ __forceinline__ uint32_t smem_u32(const void* p) {
    uint32_t a;
    asm("{ .reg .u64 t; cvta.to.shared.u64 t, %1; cvt.u32.u64 %0, t; }"
        : "=r"(a) : "l"(p));
    return a;
}
__device__ __forceinline__ uint32_t pack2h(__half a, __half b) {
    return (uint32_t)__half_as_ushort(a) |
           ((uint32_t)__half_as_ushort(b) << 16);
}

#define CP16(d, s) \
    asm volatile("cp.async.cg.shared.global [%0], [%1], 16;" :: "r"(d), "l"(s))
#define CP_COMMIT() asm volatile("cp.async.commit_group;" ::: "memory")
#define CP_WAIT(n)  asm volatile("cp.async.wait_group %0;" :: "n"(n) : "memory")

#define LDM4(r, addr) \
    asm volatile("ldmatrix.sync.aligned.m8n8.x4.shared.b16 {%0,%1,%2,%3},[%4];" \
        : "=r"((r)[0]), "=r"((r)[1]), "=r"((r)[2]), "=r"((r)[3]) : "r"(addr))

#define MMAH(d, a, b) \
    asm volatile("mma.sync.aligned.m16n8k16.row.col.f32.f16.f16.f32 " \
        "{%0,%1,%2,%3},{%4,%5,%6,%7},{%8,%9},{%0,%1,%2,%3};" \
        : "+f"((d)[0]), "+f"((d)[1]), "+f"((d)[2]), "+f"((d)[3]) \
        : "r"((a)[0]), "r"((a)[1]), "r"((a)[2]), "r"((a)[3]), \
          "r"((b)[0]), "r"((b)[1]))

// ---------------------------------------------------------------------------
// Kernel 1: per-batch alpha sum, scale, n_hat partial
// ---------------------------------------------------------------------------
__global__ void alpha_kernel(const float* __restrict__ hs,
                             const int* __restrict__ lengths) {
    int b = blockIdx.x;
    const float* base = hs + (size_t)b * TT * HH + (HH - 1);
    float s = 0.f;
    for (int t = threadIdx.x; t < TT; t += blockDim.x)
        s += 1.f / (1.f + expf(-base[(size_t)t * HH]));
    __shared__ float red[256];
    red[threadIdx.x] = s;
    __syncthreads();
    for (int o = 128; o > 0; o >>= 1) {
        if (threadIdx.x < o) red[threadIdx.x] += red[threadIdx.x + o];
        __syncthreads();
    }
    if (threadIdx.x == 0) {
        float sum = red[0];
        int li = lengths[b];
        float tll = (float)(li < LQ ? li : LQ);
        g_scale[b] = tll / sum;
        float d = tll - sum;
        g_nhat_part[b] = d * d;
    }
}
__global__ void nhat_kernel(float* __restrict__ out) {
    float v = g_nhat_part[threadIdx.x];
    #pragma unroll
    for (int o = 16; o > 0; o >>= 1) v += __shfl_down_sync(0xffffffffu, v, o);
    if (threadIdx.x == 0) out[0] = v;
}

// ---------------------------------------------------------------------------
// Kernel 2: CIF scan -> fp16 plane. Pad lane 767 -> zeros.
// ---------------------------------------------------------------------------
__global__ void cif_scan_kernel(const float* __restrict__ hs) {
    int b = blockIdx.y;
    int f = blockIdx.x * blockDim.x + threadIdx.x;
    __shared__ float s_alpha[LQ];
    float scale = g_scale[b];
    const float* hb = hs + (size_t)b * TT * HH;
    for (int t = threadIdx.x; t < LQ; t += blockDim.x)
        s_alpha[t] = scale / (1.f + expf(-hb[(size_t)t * HH + (HH - 1)]));
    __syncthreads();

    bool valid = (f < HM1);
    const float* hcol = hb + f;
    size_t obase = (size_t)b * LQ * HH + f;

    float a_r = 0.f, s_r = 0.f;
    float h = valid ? hcol[0] : 0.f;
    for (int t = 0; t < LQ; ++t) {
        float hn = valid ? hcol[(size_t)(t + 1) * HH] : 0.f;
        float a = s_alpha[t];
        float a_a = a + a_r;
        float rem = 1.0f - a_r;
        float s_a_nf = s_r + a * h;
        float s_a;
        if (a_a >= 1.0f) {
            float a_r_f = a - rem;
            s_a = s_r + rem * h;
            a_r = a_r_f;
            s_r = a_r_f * h;
        } else {
            a_r = a_a; s_a = s_a_nf; s_r = s_a_nf;
        }
        g_sa[obase + (size_t)t * HH] = __float2half_rn(s_a);
        h = hn;
    }
}

// ---------------------------------------------------------------------------
// Kernel 3: W transpose: Wt[n][k] = fp16(W[k][n]), k>=Kvalid -> 0
// ---------------------------------------------------------------------------
__global__ void wtrans_kernel(const float* __restrict__ W,
                              __half* __restrict__ Wt, int Kvalid) {
    __shared__ float t[32][33];
    int n = blockIdx.x * 32 + threadIdx.x;
    #pragma unroll
    for (int j = 0; j < 32; j += 8) {
        int k = blockIdx.y * 32 + threadIdx.y + j;
        t[threadIdx.y + j][threadIdx.x] = (k < Kvalid) ? W[(size_t)k * HH + n] : 0.f;
    }
    __syncthreads();
    #pragma unroll
    for (int j = 0; j < 32; j += 8) {
        int nn = blockIdx.x * 32 + threadIdx.y + j;
        int kk = blockIdx.y * 32 + threadIdx.x;
        Wt[(size_t)nn * HH + kk] = __float2half_rn(t[threadIdx.x][threadIdx.y + j]);
    }
}

// ---------------------------------------------------------------------------
// Kernel 4: single-term fp16 HMMA GEMM. CTA tile 128x128, 256 threads /
// 8 warps (2x4, warp tile 64x32 — 16 MMA per 6 LDSM). K chunks of 64,
// 3-stage cp.async pipeline, XOR-swizzled SMEM.
// MODE 0: y1 = relu(A@B^T+b) -> fp16. MODE 1: fc + bert_mixing.
// ---------------------------------------------------------------------------
#define KCH 64
#define NCHUNK (HH / KCH)            /* 12 */
#define MAT_BYTES 16384              /* 128 rows x 128B */
#define STAGE_BYTES (2 * MAT_BYTES)  /* 32768: A, B */
#define NSTAGE 3
#define SMEM_SZ (NSTAGE * STAGE_BYTES) /* 98304 */

template <int MODE>
__global__ void __launch_bounds__(256, 1)
gemm_hmma(const __half* __restrict__ Ah, const __half* __restrict__ Bh,
          const float* __restrict__ bias,
          __half* __restrict__ yout,
          float* __restrict__ outbm, float* __restrict__ fcout,
          const float* __restrict__ bert, const float* __restrict__ mixu) {
    extern __shared__ char smem[];
    uint32_t sb = smem_u32(smem);
    int tid = threadIdx.x, lane = tid & 31, wid = tid >> 5;
    int row0 = blockIdx.y * 128, col0 = blockIdx.x * 128;
    int wr = wid >> 2, wc = wid & 3;     // warp tile: rows wr*64, cols wc*32

    float acc[4][4][4];
    #pragma unroll
    for (int i = 0; i < 4; ++i)
        #pragma unroll
        for (int j = 0; j < 4; ++j)
            #pragma unroll
            for (int d = 0; d < 4; ++d) acc[i][j][d] = 0.f;

    int cr = tid >> 3, cu = tid & 7;     // 256 thr: rows 0..31 (+32/q), units 0..7

    int a_row = lane & 15;
    int a_un  = lane >> 4;
    int b_row = (lane & 7) + ((lane & 16) >> 1);
    int b_un  = (lane & 8) >> 3;

    #define LOAD_CHUNK(s, ci) do {                                            \
        int k0e = (ci) * KCH;                                                 \
        uint32_t db = sb + (s) * STAGE_BYTES;                                 \
        _Pragma("unroll")                                                     \
        for (int q = 0; q < 4; ++q) {                                         \
            int r = cr + q * 32;                                              \
            uint32_t d = db + r * 128 + ((cu ^ (r & 7)) << 4);                \
            size_t eA = (size_t)(row0 + r) * HH + k0e + cu * 8;               \
            size_t eB = (size_t)(col0 + r) * HH + k0e + cu * 8;               \
            CP16(d,             (const char*)(Ah + eA));                      \
            CP16(d + MAT_BYTES, (const char*)(Bh + eB));                      \
        }                                                                     \
        CP_COMMIT();                                                          \
    } while (0)

    LOAD_CHUNK(0, 0);
    LOAD_CHUNK(1, 1);

    for (int i = 0; i < NCHUNK; ++i) {
        if (i + 2 < NCHUNK) { LOAD_CHUNK((i + 2) % NSTAGE, i + 2); CP_WAIT(2); }
        else if (i == NCHUNK - 2) CP_WAIT(1);
        else                      CP_WAIT(0);
        __syncthreads();

        uint32_t base = sb + (i % NSTAGE) * STAGE_BYTES;
        #pragma unroll
        for (int kk = 0; kk < KCH; kk += 16) {
            uint32_t ah[4][4], bh[4][2];
            #pragma unroll
            for (int m = 0; m < 4; ++m) {
                int r = wr * 64 + m * 16 + a_row;
                int un = (kk >> 3) + a_un;
                uint32_t off = base + r * 128 + ((un ^ (r & 7)) << 4);
                LDM4(ah[m], off);
            }
            #pragma unroll
            for (int jp = 0; jp < 2; ++jp) {
                int r = wc * 32 + jp * 16 + b_row;
                int un = (kk >> 3) + b_un;
                uint32_t off = base + MAT_BYTES + r * 128 + ((un ^ (r & 7)) << 4);
                uint32_t t0[4];
                LDM4(t0, off);
                bh[2*jp][0] = t0[0]; bh[2*jp][1] = t0[1];
                bh[2*jp+1][0] = t0[2]; bh[2*jp+1][1] = t0[3];
            }
            #pragma unroll
            for (int m = 0; m < 4; ++m)
                #pragma unroll
                for (int j = 0; j < 4; ++j)
                    MMAH(acc[m][j], ah[m], bh[j]);
        }
        __syncthreads();
    }

    // ---- epilogue: registers -> global (fused bias / relu / mix) ----
    int tr = lane >> 2;
    int tc = (lane & 3) * 2;
    #pragma unroll
    for (int m = 0; m < 4; ++m) {
        #pragma unroll
        for (int half = 0; half < 2; ++half) {
            int row = row0 + wr * 64 + m * 16 + half * 8 + tr;
            float msk = 0.f;
            if (MODE == 1) msk = (mixu[row] < P_MIX_C) ? 1.f : 0.f;
            #pragma unroll
            for (int j = 0; j < 4; ++j) {
                int col = col0 + wc * 32 + j * 8 + tc;
                float v0 = acc[m][j][half * 2 + 0] + bias[col];
                float v1 = acc[m][j][half * 2 + 1] + bias[col + 1];
                size_t idx = (size_t)row * HH + col;
                if (MODE == 0) {
                    v0 = fmaxf(v0, 0.f); v1 = fmaxf(v1, 0.f);
                    *(uint32_t*)(yout + idx) =
                        pack2h(__float2half_rn(v0), __float2half_rn(v1));
                } else {
                    float2 fcv = make_float2(v0, v1);
                    *(float2*)(fcout + idx) = fcv;
                    float2 bm = fcv;
                    if (msk != 0.f) bm = *(const float2*)(bert + idx);
                    *(float2*)(outbm + idx) = bm;
                }
            }
        }
    }
}

// ---------------------------------------------------------------------------
extern "C" void kernel_launch(void* const* d_in, const int* in_sizes, int n_in,
                              void* d_out, int out_size) {
    const float* hs      = (const float*)d_in[0];
    const int*   lengths = (const int*)  d_in[1];
    const float* W1      = (const float*)d_in[2];
    const float* b1      = (const float*)d_in[3];
    const float* W2      = (const float*)d_in[4];
    const float* b2      = (const float*)d_in[5];
    const float* bert    = (const float*)d_in[6];
    const float* mixu    = (const float*)d_in[7];
    float* out = (float*)d_out;

    __half *sa, *y1, *w1t, *w2t;
    cudaGetSymbolAddress((void**)&sa, g_sa);
    cudaGetSymbolAddress((void**)&y1, g_y1);
    cudaGetSymbolAddress((void**)&w1t, g_w1t);
    cudaGetSymbolAddress((void**)&w2t, g_w2t);

    cudaFuncSetAttribute(gemm_hmma<0>, cudaFuncAttributeMaxDynamicSharedMemorySize, SMEM_SZ);
    cudaFuncSetAttribute(gemm_hmma<1>, cudaFuncAttributeMaxDynamicSharedMemorySize, SMEM_SZ);

    alpha_kernel<<<BB, 256>>>(hs, lengths);
    nhat_kernel<<<1, 32>>>(out + NHAT_OFF);
    wtrans_kernel<<<dim3(24, 24), dim3(32, 8)>>>(W1, w1t, HM1);
    wtrans_kernel<<<dim3(24, 24), dim3(32, 8)>>>(W2, w2t, HH);
    cif_scan_kernel<<<dim3(3, BB), 256>>>(hs);

    gemm_hmma<0><<<dim3(6, 100), 256, SMEM_SZ>>>(
        sa, w1t, b1, y1, nullptr, nullptr, nullptr, nullptr);
    gemm_hmma<1><<<dim3(6, 100), 256, SMEM_SZ>>>(
        y1, w2t, b2, nullptr,
        out /*bert_mixing*/, out + FC_OFF /*fc*/, bert, mixu);
}

// round 10
// speedup vs baseline: 1.0838x; 1.0838x over previous
#include <cuda_runtime.h>
#include <cuda.h>
#include <cuda_fp16.h>
#include <math.h>
#include <stdint.h>

#define BB 32
#define TT 1500
#define HH 768
#define HM1 767
#define LQ 400
#define MM (BB*LQ)                 /* 12800 */
#define FC_OFF ((size_t)MM*HH)
#define NHAT_OFF ((size_t)2*MM*HH)
#define P_MIX_C 0.15f

// ---------------- scratch (__device__ globals, no allocs) ------------------
__device__ float g_scale[BB];
__device__ float g_nhat_part[BB];
__device__ __half g_sa[(size_t)MM * HH];
__device__ __half g_y1[(size_t)MM * HH];
__device__ __half g_w1t[(size_t)HH * HH];
__device__ __half g_w2t[(size_t)HH * HH];

// ---------------- helpers --------------------------------------------------
__device__ __forceinline__ uint32_t smem_u32(const void* p) {
    uint32_t a;
    asm("{ .reg .u64 t; cvta.to.shared.u64 t, %1; cvt.u32.u64 %0, t; }"
        : "=r"(a) : "l"(p));
    return a;
}
__device__ __forceinline__ uint32_t pack2h(__half a, __half b) {
    return (uint32_t)__half_as_ushort(a) |
           ((uint32_t)__half_as_ushort(b) << 16);
}

#define LDM4(r, addr) \
    asm volatile("ldmatrix.sync.aligned.m8n8.x4.shared.b16 {%0,%1,%2,%3},[%4];" \
        : "=r"((r)[0]), "=r"((r)[1]), "=r"((r)[2]), "=r"((r)[3]) : "r"(addr))

#define MMAH(d, a, b) \
    asm volatile("mma.sync.aligned.m16n8k16.row.col.f32.f16.f16.f32 " \
        "{%0,%1,%2,%3},{%4,%5,%6,%7},{%8,%9},{%0,%1,%2,%3};" \
        : "+f"((d)[0]), "+f"((d)[1]), "+f"((d)[2]), "+f"((d)[3]) \
        : "r"((a)[0]), "r"((a)[1]), "r"((a)[2]), "r"((a)[3]), \
          "r"((b)[0]), "r"((b)[1]))

#define MBAR_INIT(mbar, cnt) \
    asm volatile("mbarrier.init.shared.b64 [%0], %1;" :: "r"(mbar), "r"(cnt) : "memory")
#define MBAR_EXPECT_TX(mbar, bytes) \
    asm volatile("mbarrier.arrive.expect_tx.shared.b64 _, [%0], %1;" \
                 :: "r"(mbar), "r"(bytes) : "memory")
#define MBAR_WAIT(mbar, par) do {                                             \
    uint32_t _m = (mbar), _p = (par), _d;                                     \
    asm volatile("{\n\t.reg .pred p;\n\t"                                     \
        "mbarrier.try_wait.parity.acquire.cta.shared::cta.b64 p, [%1], %2;\n\t"\
        "selp.b32 %0, 1, 0, p;\n\t}" : "=r"(_d) : "r"(_m), "r"(_p) : "memory");\
    if (!_d) {                                                                \
        asm volatile("{\n\t.reg .pred P1;\n\t"                                \
        "WL_%=:\n\t"                                                          \
        "mbarrier.try_wait.parity.acquire.cta.shared::cta.b64 P1, [%0], %1, 0x989680;\n\t"\
        "@P1 bra.uni WD_%=;\n\tbra.uni WL_%=;\n\tWD_%=:\n\t}"                 \
        :: "r"(_m), "r"(_p) : "memory");                                      \
    } } while (0)

#define TMA2D(smemaddr, mapptr, x, y, mbar) \
    asm volatile("cp.async.bulk.tensor.2d.shared::cta.global.tile.mbarrier::complete_tx::bytes " \
                 "[%0], [%1, {%2, %3}], [%4];" \
                 :: "r"(smemaddr), "l"(mapptr), "r"(x), "r"(y), "r"(mbar) : "memory")

// ---------------------------------------------------------------------------
// Kernel 1: per-batch alpha sum, scale, n_hat partial
// ---------------------------------------------------------------------------
__global__ void alpha_kernel(const float* __restrict__ hs,
                             const int* __restrict__ lengths) {
    int b = blockIdx.x;
    const float* base = hs + (size_t)b * TT * HH + (HH - 1);
    float s = 0.f;
    for (int t = threadIdx.x; t < TT; t += blockDim.x)
        s += 1.f / (1.f + expf(-base[(size_t)t * HH]));
    __shared__ float red[256];
    red[threadIdx.x] = s;
    __syncthreads();
    for (int o = 128; o > 0; o >>= 1) {
        if (threadIdx.x < o) red[threadIdx.x] += red[threadIdx.x + o];
        __syncthreads();
    }
    if (threadIdx.x == 0) {
        float sum = red[0];
        int li = lengths[b];
        float tll = (float)(li < LQ ? li : LQ);
        g_scale[b] = tll / sum;
        float d = tll - sum;
        g_nhat_part[b] = d * d;
    }
}
__global__ void nhat_kernel(float* __restrict__ out) {
    float v = g_nhat_part[threadIdx.x];
    #pragma unroll
    for (int o = 16; o > 0; o >>= 1) v += __shfl_down_sync(0xffffffffu, v, o);
    if (threadIdx.x == 0) out[0] = v;
}

// ---------------------------------------------------------------------------
// Kernel 2: CIF scan -> fp16 plane. Pad lane 767 -> zeros.
// ---------------------------------------------------------------------------
__global__ void cif_scan_kernel(const float* __restrict__ hs) {
    int b = blockIdx.y;
    int f = blockIdx.x * blockDim.x + threadIdx.x;
    __shared__ float s_alpha[LQ];
    float scale = g_scale[b];
    const float* hb = hs + (size_t)b * TT * HH;
    for (int t = threadIdx.x; t < LQ; t += blockDim.x)
        s_alpha[t] = scale / (1.f + expf(-hb[(size_t)t * HH + (HH - 1)]));
    __syncthreads();

    bool valid = (f < HM1);
    const float* hcol = hb + f;
    size_t obase = (size_t)b * LQ * HH + f;

    float a_r = 0.f, s_r = 0.f;
    float h = valid ? hcol[0] : 0.f;
    for (int t = 0; t < LQ; ++t) {
        float hn = valid ? hcol[(size_t)(t + 1) * HH] : 0.f;
        float a = s_alpha[t];
        float a_a = a + a_r;
        float rem = 1.0f - a_r;
        float s_a_nf = s_r + a * h;
        float s_a;
        if (a_a >= 1.0f) {
            float a_r_f = a - rem;
            s_a = s_r + rem * h;
            a_r = a_r_f;
            s_r = a_r_f * h;
        } else {
            a_r = a_a; s_a = s_a_nf; s_r = s_a_nf;
        }
        g_sa[obase + (size_t)t * HH] = __float2half_rn(s_a);
        h = hn;
    }
}

// ---------------------------------------------------------------------------
// Kernel 3: W transpose: Wt[n][k] = fp16(W[k][n]), k>=Kvalid -> 0
// ---------------------------------------------------------------------------
__global__ void wtrans_kernel(const float* __restrict__ W,
                              __half* __restrict__ Wt, int Kvalid) {
    __shared__ float t[32][33];
    int n = blockIdx.x * 32 + threadIdx.x;
    #pragma unroll
    for (int j = 0; j < 32; j += 8) {
        int k = blockIdx.y * 32 + threadIdx.y + j;
        t[threadIdx.y + j][threadIdx.x] = (k < Kvalid) ? W[(size_t)k * HH + n] : 0.f;
    }
    __syncthreads();
    #pragma unroll
    for (int j = 0; j < 32; j += 8) {
        int nn = blockIdx.x * 32 + threadIdx.y + j;
        int kk = blockIdx.y * 32 + threadIdx.x;
        Wt[(size_t)nn * HH + kk] = __float2half_rn(t[threadIdx.x][threadIdx.y + j]);
    }
}

// ---------------------------------------------------------------------------
// Kernel 4: fp16 HMMA GEMM with TMA feed. CTA tile 128x128, 512 threads /
// 16 warps (4x4, warp tile 32x32). K chunks of 64, 4-stage TMA+mbarrier
// pipeline (TMA SW128 swizzle == our ldmatrix XOR swizzle).
// MODE 0: y1 = relu(A@B^T+b) -> fp16. MODE 1: fc + bert_mixing.
// ---------------------------------------------------------------------------
#define KCH 64
#define NCHUNK (HH / KCH)            /* 12 */
#define MATB 16384                   /* 128 rows x 128B */
#define STAGEB 32768                 /* A + B */
#define NSTAGE 4
#define SOFF 1024
#define SMEM_SZ (SOFF + NSTAGE * STAGEB)   /* 132096 */

template <int MODE>
__global__ void __launch_bounds__(512, 1)
gemm_tma(const __grid_constant__ CUtensorMap tmA,
         const __grid_constant__ CUtensorMap tmB,
         const float* __restrict__ bias,
         __half* __restrict__ yout,
         float* __restrict__ outbm, float* __restrict__ fcout,
         const float* __restrict__ bert, const float* __restrict__ mixu) {
    extern __shared__ char smem[];
    uint32_t sb = smem_u32(smem);
    int tid = threadIdx.x, lane = tid & 31, wid = tid >> 5;
    int row0 = blockIdx.y * 128, col0 = blockIdx.x * 128;
    int wr = wid >> 2, wc = wid & 3;     // warp tile: rows wr*32, cols wc*32

    if (tid == 0) {
        #pragma unroll
        for (int s = 0; s < NSTAGE; ++s) MBAR_INIT(sb + s * 8, 1);
    }
    __syncthreads();

    // prologue: issue chunks 0..NSTAGE-2
    if (tid == 0) {
        #pragma unroll
        for (int c = 0; c < NSTAGE - 1; ++c) {
            uint32_t st = sb + SOFF + c * STAGEB;
            MBAR_EXPECT_TX(sb + c * 8, STAGEB);
            TMA2D(st,        &tmA, c * KCH, row0, sb + c * 8);
            TMA2D(st + MATB, &tmB, c * KCH, col0, sb + c * 8);
        }
    }

    float acc[2][4][4];
    #pragma unroll
    for (int i = 0; i < 2; ++i)
        #pragma unroll
        for (int j = 0; j < 4; ++j)
            #pragma unroll
            for (int d = 0; d < 4; ++d) acc[i][j][d] = 0.f;

    int a_row = lane & 15;
    int a_un  = lane >> 4;
    int b_row = (lane & 7) + ((lane & 16) >> 1);
    int b_un  = (lane & 8) >> 3;

    for (int i = 0; i < NCHUNK; ++i) {
        // issue chunk i+NSTAGE-1 into stage (i-1)%NSTAGE (freed at end of i-1)
        if (tid == 0 && i + NSTAGE - 1 < NCHUNK) {
            int c = i + NSTAGE - 1;
            int s = c & (NSTAGE - 1);
            uint32_t st = sb + SOFF + s * STAGEB;
            MBAR_EXPECT_TX(sb + s * 8, STAGEB);
            TMA2D(st,        &tmA, c * KCH, row0, sb + s * 8);
            TMA2D(st + MATB, &tmB, c * KCH, col0, sb + s * 8);
        }
        MBAR_WAIT(sb + (i & (NSTAGE - 1)) * 8, (i >> 2) & 1);

        uint32_t base = sb + SOFF + (i & (NSTAGE - 1)) * STAGEB;
        #pragma unroll
        for (int kk = 0; kk < KCH; kk += 16) {
            uint32_t ah[2][4], bh[4][2];
            #pragma unroll
            for (int m = 0; m < 2; ++m) {
                int r = wr * 32 + m * 16 + a_row;
                int un = (kk >> 3) + a_un;
                uint32_t off = base + r * 128 + ((un ^ (r & 7)) << 4);
                LDM4(ah[m], off);
            }
            #pragma unroll
            for (int jp = 0; jp < 2; ++jp) {
                int r = wc * 32 + jp * 16 + b_row;
                int un = (kk >> 3) + b_un;
                uint32_t off = base + MATB + r * 128 + ((un ^ (r & 7)) << 4);
                uint32_t t0[4];
                LDM4(t0, off);
                bh[2*jp][0] = t0[0]; bh[2*jp][1] = t0[1];
                bh[2*jp+1][0] = t0[2]; bh[2*jp+1][1] = t0[3];
            }
            #pragma unroll
            for (int m = 0; m < 2; ++m)
                #pragma unroll
                for (int j = 0; j < 4; ++j)
                    MMAH(acc[m][j], ah[m], bh[j]);
        }
        __syncthreads();                 // stage (i % NSTAGE) now reusable
    }

    // ---- epilogue: registers -> global (fused bias / relu / mix) ----
    int tr = lane >> 2;
    int tc = (lane & 3) * 2;
    #pragma unroll
    for (int m = 0; m < 2; ++m) {
        #pragma unroll
        for (int half = 0; half < 2; ++half) {
            int row = row0 + wr * 32 + m * 16 + half * 8 + tr;
            float msk = 0.f;
            if (MODE == 1) msk = (mixu[row] < P_MIX_C) ? 1.f : 0.f;
            #pragma unroll
            for (int j = 0; j < 4; ++j) {
                int col = col0 + wc * 32 + j * 8 + tc;
                float v0 = acc[m][j][half * 2 + 0] + bias[col];
                float v1 = acc[m][j][half * 2 + 1] + bias[col + 1];
                size_t idx = (size_t)row * HH + col;
                if (MODE == 0) {
                    v0 = fmaxf(v0, 0.f); v1 = fmaxf(v1, 0.f);
                    *(uint32_t*)(yout + idx) =
                        pack2h(__float2half_rn(v0), __float2half_rn(v1));
                } else {
                    float2 fcv = make_float2(v0, v1);
                    *(float2*)(fcout + idx) = fcv;
                    float2 bm = fcv;
                    if (msk != 0.f) bm = *(const float2*)(bert + idx);
                    *(float2*)(outbm + idx) = bm;
                }
            }
        }
    }
}

// ---------------------------------------------------------------------------
typedef CUresult (*TmEncodeFn)(CUtensorMap*, CUtensorMapDataType, cuuint32_t,
                               void*, const cuuint64_t*, const cuuint64_t*,
                               const cuuint32_t*, const cuuint32_t*,
                               CUtensorMapInterleave, CUtensorMapSwizzle,
                               CUtensorMapL2promotion, CUtensorMapFloatOOBfill);

static void encode_map(TmEncodeFn fn, CUtensorMap* m, void* base, cuuint64_t rows) {
    cuuint64_t dims[2]    = {HH, rows};
    cuuint64_t strides[1] = {HH * sizeof(__half)};   /* 1536 B */
    cuuint32_t box[2]     = {KCH, 128};              /* 128B x 128 rows */
    cuuint32_t es[2]      = {1, 1};
    fn(m, CU_TENSOR_MAP_DATA_TYPE_FLOAT16, 2, base, dims, strides, box, es,
       CU_TENSOR_MAP_INTERLEAVE_NONE, CU_TENSOR_MAP_SWIZZLE_128B,
       CU_TENSOR_MAP_L2_PROMOTION_L2_128B, CU_TENSOR_MAP_FLOAT_OOB_FILL_NONE);
}

extern "C" void kernel_launch(void* const* d_in, const int* in_sizes, int n_in,
                              void* d_out, int out_size) {
    const float* hs      = (const float*)d_in[0];
    const int*   lengths = (const int*)  d_in[1];
    const float* W1      = (const float*)d_in[2];
    const float* b1      = (const float*)d_in[3];
    const float* W2      = (const float*)d_in[4];
    const float* b2      = (const float*)d_in[5];
    const float* bert    = (const float*)d_in[6];
    const float* mixu    = (const float*)d_in[7];
    float* out = (float*)d_out;

    __half *sa, *y1, *w1t, *w2t;
    cudaGetSymbolAddress((void**)&sa, g_sa);
    cudaGetSymbolAddress((void**)&y1, g_y1);
    cudaGetSymbolAddress((void**)&w1t, g_w1t);
    cudaGetSymbolAddress((void**)&w2t, g_w2t);

    // TMA tensormaps (driver entry point -> no -lcuda link dependency)
    void* fnp = nullptr;
    cudaDriverEntryPointQueryResult qr;
    cudaGetDriverEntryPoint("cuTensorMapEncodeTiled", &fnp,
                            cudaEnableDefault, &qr);
    TmEncodeFn enc = (TmEncodeFn)fnp;
    CUtensorMap tmA1, tmB1, tmA2, tmB2;
    encode_map(enc, &tmA1, sa,  MM);
    encode_map(enc, &tmB1, w1t, HH);
    encode_map(enc, &tmA2, y1,  MM);
    encode_map(enc, &tmB2, w2t, HH);

    cudaFuncSetAttribute(gemm_tma<0>, cudaFuncAttributeMaxDynamicSharedMemorySize, SMEM_SZ);
    cudaFuncSetAttribute(gemm_tma<1>, cudaFuncAttributeMaxDynamicSharedMemorySize, SMEM_SZ);

    alpha_kernel<<<BB, 256>>>(hs, lengths);
    nhat_kernel<<<1, 32>>>(out + NHAT_OFF);
    wtrans_kernel<<<dim3(24, 24), dim3(32, 8)>>>(W1, w1t, HM1);
    wtrans_kernel<<<dim3(24, 24), dim3(32, 8)>>>(W2, w2t, HH);
    cif_scan_kernel<<<dim3(3, BB), 256>>>(hs);

    gemm_tma<0><<<dim3(6, 100), 512, SMEM_SZ>>>(
        tmA1, tmB1, b1, y1, nullptr, nullptr, nullptr, nullptr);
    gemm_tma<1><<<dim3(6, 100), 512, SMEM_SZ>>>(
        tmA2, tmB2, b2, nullptr,
        out /*bert_mixing*/, out + FC_OFF /*fc*/, bert, mixu);
}

// round 11
// speedup vs baseline: 1.2199x; 1.1256x over previous
#include <cuda_runtime.h>
#include <cuda.h>
#include <cuda_fp16.h>
#include <math.h>
#include <stdint.h>

#define BB 32
#define TT 1500
#define HH 768
#define HM1 767
#define LQ 400
#define MM (BB*LQ)                 /* 12800 */
#define FC_OFF ((size_t)MM*HH)
#define NHAT_OFF ((size_t)2*MM*HH)
#define P_MIX_C 0.15f

// ---------------- scratch (__device__ globals, no allocs) ------------------
__device__ float g_scale[BB];
__device__ float g_nhat_part[BB];
__device__ __half g_sa[(size_t)MM * HH];
__device__ __half g_y1[(size_t)MM * HH];
__device__ __half g_w1t[(size_t)HH * HH];
__device__ __half g_w2t[(size_t)HH * HH];

// ---------------- helpers --------------------------------------------------
__device__ __forceinline__ uint32_t smem_u32(const void* p) {
    uint32_t a;
    asm("{ .reg .u64 t; cvta.to.shared.u64 t, %1; cvt.u32.u64 %0, t; }"
        : "=r"(a) : "l"(p));
    return a;
}
__device__ __forceinline__ uint32_t pack2h(__half a, __half b) {
    return (uint32_t)__half_as_ushort(a) |
           ((uint32_t)__half_as_ushort(b) << 16);
}

#define LDM4(r, addr) \
    asm volatile("ldmatrix.sync.aligned.m8n8.x4.shared.b16 {%0,%1,%2,%3},[%4];" \
        : "=r"((r)[0]), "=r"((r)[1]), "=r"((r)[2]), "=r"((r)[3]) : "r"(addr))

#define MMAH(d, a, b) \
    asm volatile("mma.sync.aligned.m16n8k16.row.col.f32.f16.f16.f32 " \
        "{%0,%1,%2,%3},{%4,%5,%6,%7},{%8,%9},{%0,%1,%2,%3};" \
        : "+f"((d)[0]), "+f"((d)[1]), "+f"((d)[2]), "+f"((d)[3]) \
        : "r"((a)[0]), "r"((a)[1]), "r"((a)[2]), "r"((a)[3]), \
          "r"((b)[0]), "r"((b)[1]))

#define MBAR_INIT(mbar, cnt) \
    asm volatile("mbarrier.init.shared.b64 [%0], %1;" :: "r"(mbar), "r"(cnt) : "memory")
#define MBAR_EXPECT_TX(mbar, bytes) \
    asm volatile("mbarrier.arrive.expect_tx.shared.b64 _, [%0], %1;" \
                 :: "r"(mbar), "r"(bytes) : "memory")
#define MBAR_WAIT(mbar, par) do {                                             \
    uint32_t _m = (mbar), _p = (par), _d;                                     \
    asm volatile("{\n\t.reg .pred p;\n\t"                                     \
        "mbarrier.try_wait.parity.acquire.cta.shared::cta.b64 p, [%1], %2;\n\t"\
        "selp.b32 %0, 1, 0, p;\n\t}" : "=r"(_d) : "r"(_m), "r"(_p) : "memory");\
    if (!_d) {                                                                \
        asm volatile("{\n\t.reg .pred P1;\n\t"                                \
        "WL_%=:\n\t"                                                          \
        "mbarrier.try_wait.parity.acquire.cta.shared::cta.b64 P1, [%0], %1, 0x989680;\n\t"\
        "@P1 bra.uni WD_%=;\n\tbra.uni WL_%=;\n\tWD_%=:\n\t}"                 \
        :: "r"(_m), "r"(_p) : "memory");                                      \
    } } while (0)

#define TMA2D(smemaddr, mapptr, x, y, mbar) \
    asm volatile("cp.async.bulk.tensor.2d.shared::cta.global.tile.mbarrier::complete_tx::bytes " \
                 "[%0], [%1, {%2, %3}], [%4];" \
                 :: "r"(smemaddr), "l"(mapptr), "r"(x), "r"(y), "r"(mbar) : "memory")

// ---------------------------------------------------------------------------
// Kernel 1: per-batch alpha sum, scale, n_hat partial
// ---------------------------------------------------------------------------
__global__ void alpha_kernel(const float* __restrict__ hs,
                             const int* __restrict__ lengths) {
    int b = blockIdx.x;
    const float* base = hs + (size_t)b * TT * HH + (HH - 1);
    float s = 0.f;
    for (int t = threadIdx.x; t < TT; t += blockDim.x)
        s += 1.f / (1.f + expf(-base[(size_t)t * HH]));
    __shared__ float red[256];
    red[threadIdx.x] = s;
    __syncthreads();
    for (int o = 128; o > 0; o >>= 1) {
        if (threadIdx.x < o) red[threadIdx.x] += red[threadIdx.x + o];
        __syncthreads();
    }
    if (threadIdx.x == 0) {
        float sum = red[0];
        int li = lengths[b];
        float tll = (float)(li < LQ ? li : LQ);
        g_scale[b] = tll / sum;
        float d = tll - sum;
        g_nhat_part[b] = d * d;
    }
}
__global__ void nhat_kernel(float* __restrict__ out) {
    float v = g_nhat_part[threadIdx.x];
    #pragma unroll
    for (int o = 16; o > 0; o >>= 1) v += __shfl_down_sync(0xffffffffu, v, o);
    if (threadIdx.x == 0) out[0] = v;
}

// ---------------------------------------------------------------------------
// Kernel 2: CIF scan -> fp16 plane. Pad lane 767 -> zeros.
// ---------------------------------------------------------------------------
__global__ void cif_scan_kernel(const float* __restrict__ hs) {
    int b = blockIdx.y;
    int f = blockIdx.x * blockDim.x + threadIdx.x;
    __shared__ float s_alpha[LQ];
    float scale = g_scale[b];
    const float* hb = hs + (size_t)b * TT * HH;
    for (int t = threadIdx.x; t < LQ; t += blockDim.x)
        s_alpha[t] = scale / (1.f + expf(-hb[(size_t)t * HH + (HH - 1)]));
    __syncthreads();

    bool valid = (f < HM1);
    const float* hcol = hb + f;
    size_t obase = (size_t)b * LQ * HH + f;

    float a_r = 0.f, s_r = 0.f;
    float h = valid ? hcol[0] : 0.f;
    for (int t = 0; t < LQ; ++t) {
        float hn = valid ? hcol[(size_t)(t + 1) * HH] : 0.f;
        float a = s_alpha[t];
        float a_a = a + a_r;
        float rem = 1.0f - a_r;
        float s_a_nf = s_r + a * h;
        float s_a;
        if (a_a >= 1.0f) {
            float a_r_f = a - rem;
            s_a = s_r + rem * h;
            a_r = a_r_f;
            s_r = a_r_f * h;
        } else {
            a_r = a_a; s_a = s_a_nf; s_r = s_a_nf;
        }
        g_sa[obase + (size_t)t * HH] = __float2half_rn(s_a);
        h = hn;
    }
}

// ---------------------------------------------------------------------------
// Kernel 3: W transpose: Wt[n][k] = fp16(W[k][n]), k>=Kvalid -> 0
// ---------------------------------------------------------------------------
__global__ void wtrans_kernel(const float* __restrict__ W,
                              __half* __restrict__ Wt, int Kvalid) {
    __shared__ float t[32][33];
    int n = blockIdx.x * 32 + threadIdx.x;
    #pragma unroll
    for (int j = 0; j < 32; j += 8) {
        int k = blockIdx.y * 32 + threadIdx.y + j;
        t[threadIdx.y + j][threadIdx.x] = (k < Kvalid) ? W[(size_t)k * HH + n] : 0.f;
    }
    __syncthreads();
    #pragma unroll
    for (int j = 0; j < 32; j += 8) {
        int nn = blockIdx.x * 32 + threadIdx.y + j;
        int kk = blockIdx.y * 32 + threadIdx.x;
        Wt[(size_t)nn * HH + kk] = __float2half_rn(t[threadIdx.x][threadIdx.y + j]);
    }
}

// ---------------------------------------------------------------------------
// Kernel 4: fp16 HMMA GEMM, TMA feed, 2 CTAs/SM. CTA tile 128x128, 256
// threads / 8 warps (2x4, warp tile 64x32 — R3-validated geometry).
// 3-stage TMA+mbarrier pipeline (97KB smem -> two CTAs co-resident; one
// CTA's barrier/epilogue gaps are hidden by the other's MMA issue).
// MODE 0: y1 = relu(A@B^T+b) -> fp16. MODE 1: fc + bert_mixing.
// ---------------------------------------------------------------------------
#define KCH 64
#define NCHUNK (HH / KCH)            /* 12 */
#define MATB 16384                   /* 128 rows x 128B */
#define STAGEB 32768                 /* A + B */
#define NSTAGE 3
#define SOFF 1024
#define SMEM_SZ (SOFF + NSTAGE * STAGEB)   /* 99328 */

template <int MODE>
__global__ void __launch_bounds__(256, 2)
gemm_tma(const __grid_constant__ CUtensorMap tmA,
         const __grid_constant__ CUtensorMap tmB,
         const float* __restrict__ bias,
         __half* __restrict__ yout,
         float* __restrict__ outbm, float* __restrict__ fcout,
         const float* __restrict__ bert, const float* __restrict__ mixu) {
    extern __shared__ char smem[];
    uint32_t sb = smem_u32(smem);
    int tid = threadIdx.x, lane = tid & 31, wid = tid >> 5;
    int row0 = blockIdx.y * 128, col0 = blockIdx.x * 128;
    int wr = wid >> 2, wc = wid & 3;     // warp tile: rows wr*64, cols wc*32

    if (tid == 0) {
        #pragma unroll
        for (int s = 0; s < NSTAGE; ++s) MBAR_INIT(sb + s * 8, 1);
    }
    __syncthreads();

    // prologue: issue chunks 0..NSTAGE-2
    if (tid == 0) {
        #pragma unroll
        for (int c = 0; c < NSTAGE - 1; ++c) {
            uint32_t st = sb + SOFF + c * STAGEB;
            MBAR_EXPECT_TX(sb + c * 8, STAGEB);
            TMA2D(st,        &tmA, c * KCH, row0, sb + c * 8);
            TMA2D(st + MATB, &tmB, c * KCH, col0, sb + c * 8);
        }
    }

    float acc[4][4][4];
    #pragma unroll
    for (int i = 0; i < 4; ++i)
        #pragma unroll
        for (int j = 0; j < 4; ++j)
            #pragma unroll
            for (int d = 0; d < 4; ++d) acc[i][j][d] = 0.f;

    int a_row = lane & 15;
    int a_un  = lane >> 4;
    int b_row = (lane & 7) + ((lane & 16) >> 1);
    int b_un  = (lane & 8) >> 3;

    for (int i = 0; i < NCHUNK; ++i) {
        // issue chunk i+NSTAGE-1 into stage freed at end of iter i-1
        if (tid == 0 && i + NSTAGE - 1 < NCHUNK) {
            int c = i + NSTAGE - 1;
            int s = c % NSTAGE;
            uint32_t st = sb + SOFF + s * STAGEB;
            MBAR_EXPECT_TX(sb + s * 8, STAGEB);
            TMA2D(st,        &tmA, c * KCH, row0, sb + s * 8);
            TMA2D(st + MATB, &tmB, c * KCH, col0, sb + s * 8);
        }
        MBAR_WAIT(sb + (i % NSTAGE) * 8, (i / NSTAGE) & 1);

        uint32_t base = sb + SOFF + (i % NSTAGE) * STAGEB;
        #pragma unroll
        for (int kk = 0; kk < KCH; kk += 16) {
            uint32_t ah[4][4], bh[4][2];
            #pragma unroll
            for (int m = 0; m < 4; ++m) {
                int r = wr * 64 + m * 16 + a_row;
                int un = (kk >> 3) + a_un;
                uint32_t off = base + r * 128 + ((un ^ (r & 7)) << 4);
                LDM4(ah[m], off);
            }
            #pragma unroll
            for (int jp = 0; jp < 2; ++jp) {
                int r = wc * 32 + jp * 16 + b_row;
                int un = (kk >> 3) + b_un;
                uint32_t off = base + MATB + r * 128 + ((un ^ (r & 7)) << 4);
                uint32_t t0[4];
                LDM4(t0, off);
                bh[2*jp][0] = t0[0]; bh[2*jp][1] = t0[1];
                bh[2*jp+1][0] = t0[2]; bh[2*jp+1][1] = t0[3];
            }
            #pragma unroll
            for (int m = 0; m < 4; ++m)
                #pragma unroll
                for (int j = 0; j < 4; ++j)
                    MMAH(acc[m][j], ah[m], bh[j]);
        }
        __syncthreads();                 // stage (i % NSTAGE) now reusable
    }

    // ---- epilogue: registers -> global (fused bias / relu / mix) ----
    int tr = lane >> 2;
    int tc = (lane & 3) * 2;
    #pragma unroll
    for (int m = 0; m < 4; ++m) {
        #pragma unroll
        for (int half = 0; half < 2; ++half) {
            int row = row0 + wr * 64 + m * 16 + half * 8 + tr;
            float msk = 0.f;
            if (MODE == 1) msk = (mixu[row] < P_MIX_C) ? 1.f : 0.f;
            #pragma unroll
            for (int j = 0; j < 4; ++j) {
                int col = col0 + wc * 32 + j * 8 + tc;
                float v0 = acc[m][j][half * 2 + 0] + bias[col];
                float v1 = acc[m][j][half * 2 + 1] + bias[col + 1];
                size_t idx = (size_t)row * HH + col;
                if (MODE == 0) {
                    v0 = fmaxf(v0, 0.f); v1 = fmaxf(v1, 0.f);
                    *(uint32_t*)(yout + idx) =
                        pack2h(__float2half_rn(v0), __float2half_rn(v1));
                } else {
                    float2 fcv = make_float2(v0, v1);
                    *(float2*)(fcout + idx) = fcv;
                    float2 bm = fcv;
                    if (msk != 0.f) bm = *(const float2*)(bert + idx);
                    *(float2*)(outbm + idx) = bm;
                }
            }
        }
    }
}

// ---------------------------------------------------------------------------
typedef CUresult (*TmEncodeFn)(CUtensorMap*, CUtensorMapDataType, cuuint32_t,
                               void*, const cuuint64_t*, const cuuint64_t*,
                               const cuuint32_t*, const cuuint32_t*,
                               CUtensorMapInterleave, CUtensorMapSwizzle,
                               CUtensorMapL2promotion, CUtensorMapFloatOOBfill);

static void encode_map(TmEncodeFn fn, CUtensorMap* m, void* base, cuuint64_t rows) {
    cuuint64_t dims[2]    = {HH, rows};
    cuuint64_t strides[1] = {HH * sizeof(__half)};   /* 1536 B */
    cuuint32_t box[2]     = {KCH, 128};              /* 128B x 128 rows */
    cuuint32_t es[2]      = {1, 1};
    fn(m, CU_TENSOR_MAP_DATA_TYPE_FLOAT16, 2, base, dims, strides, box, es,
       CU_TENSOR_MAP_INTERLEAVE_NONE, CU_TENSOR_MAP_SWIZZLE_128B,
       CU_TENSOR_MAP_L2_PROMOTION_L2_128B, CU_TENSOR_MAP_FLOAT_OOB_FILL_NONE);
}

extern "C" void kernel_launch(void* const* d_in, const int* in_sizes, int n_in,
                              void* d_out, int out_size) {
    const float* hs      = (const float*)d_in[0];
    const int*   lengths = (const int*)  d_in[1];
    const float* W1      = (const float*)d_in[2];
    const float* b1      = (const float*)d_in[3];
    const float* W2      = (const float*)d_in[4];
    const float* b2      = (const float*)d_in[5];
    const float* bert    = (const float*)d_in[6];
    const float* mixu    = (const float*)d_in[7];
    float* out = (float*)d_out;

    __half *sa, *y1, *w1t, *w2t;
    cudaGetSymbolAddress((void**)&sa, g_sa);
    cudaGetSymbolAddress((void**)&y1, g_y1);
    cudaGetSymbolAddress((void**)&w1t, g_w1t);
    cudaGetSymbolAddress((void**)&w2t, g_w2t);

    // TMA tensormaps (driver entry point -> no -lcuda link dependency)
    void* fnp = nullptr;
    cudaDriverEntryPointQueryResult qr;
    cudaGetDriverEntryPoint("cuTensorMapEncodeTiled", &fnp,
                            cudaEnableDefault, &qr);
    TmEncodeFn enc = (TmEncodeFn)fnp;
    CUtensorMap tmA1, tmB1, tmA2, tmB2;
    encode_map(enc, &tmA1, sa,  MM);
    encode_map(enc, &tmB1, w1t, HH);
    encode_map(enc, &tmA2, y1,  MM);
    encode_map(enc, &tmB2, w2t, HH);

    cudaFuncSetAttribute(gemm_tma<0>, cudaFuncAttributeMaxDynamicSharedMemorySize, SMEM_SZ);
    cudaFuncSetAttribute(gemm_tma<1>, cudaFuncAttributeMaxDynamicSharedMemorySize, SMEM_SZ);

    alpha_kernel<<<BB, 256>>>(hs, lengths);
    nhat_kernel<<<1, 32>>>(out + NHAT_OFF);
    wtrans_kernel<<<dim3(24, 24), dim3(32, 8)>>>(W1, w1t, HM1);
    wtrans_kernel<<<dim3(24, 24), dim3(32, 8)>>>(W2, w2t, HH);
    cif_scan_kernel<<<dim3(3, BB), 256>>>(hs);

    gemm_tma<0><<<dim3(6, 100), 256, SMEM_SZ>>>(
        tmA1, tmB1, b1, y1, nullptr, nullptr, nullptr, nullptr);
    gemm_tma<1><<<dim3(6, 100), 256, SMEM_SZ>>>(
        tmA2, tmB2, b2, nullptr,
        out /*bert_mixing*/, out + FC_OFF /*fc*/, bert, mixu);
}

// round 14
// speedup vs baseline: 1.2896x; 1.0571x over previous
#include <cuda_runtime.h>
#include <cuda.h>
#include <cuda_fp16.h>
#include <math.h>
#include <stdint.h>

#define BB 32
#define TT 1500
#define HH 768
#define HM1 767
#define LQ 400
#define MM (BB*LQ)                 /* 12800 */
#define FC_OFF ((size_t)MM*HH)
#define NHAT_OFF ((size_t)2*MM*HH)
#define P_MIX_C 0.15f

#define NRB 100
#define NCB 6
#define TILES1 (NRB*NCB)           /* 600 */
#define TILES_ALL (2*TILES1)       /* 1200 */
#define NCTA 296                   /* 148 SMs x 2 CTAs */

// ---------------- scratch (__device__ globals, no allocs) ------------------
__device__ float g_scale[BB];
__device__ float g_nhat_part[BB];
__device__ int   g_tilectr;
__device__ int   g_ready[NRB];
__device__ __half g_sa[(size_t)MM * HH];
__device__ __half g_y1[(size_t)MM * HH];
__device__ __half g_w1t[(size_t)HH * HH];
__device__ __half g_w2t[(size_t)HH * HH];

// ---------------- helpers --------------------------------------------------
__device__ __forceinline__ uint32_t smem_u32(const void* p) {
    uint32_t a;
    asm("{ .reg .u64 t; cvta.to.shared.u64 t, %1; cvt.u32.u64 %0, t; }"
        : "=r"(a) : "l"(p));
    return a;
}
__device__ __forceinline__ uint32_t pack2h(__half a, __half b) {
    return (uint32_t)__half_as_ushort(a) |
           ((uint32_t)__half_as_ushort(b) << 16);
}
__device__ __forceinline__ int ld_acquire(const int* p) {
    int v;
    asm volatile("ld.global.acquire.gpu.b32 %0, [%1];" : "=r"(v) : "l"(p) : "memory");
    return v;
}

#define LDM4(r, addr) \
    asm volatile("ldmatrix.sync.aligned.m8n8.x4.shared.b16 {%0,%1,%2,%3},[%4];" \
        : "=r"((r)[0]), "=r"((r)[1]), "=r"((r)[2]), "=r"((r)[3]) : "r"(addr))

#define MMAH(d, a, b) \
    asm volatile("mma.sync.aligned.m16n8k16.row.col.f32.f16.f16.f32 " \
        "{%0,%1,%2,%3},{%4,%5,%6,%7},{%8,%9},{%0,%1,%2,%3};" \
        : "+f"((d)[0]), "+f"((d)[1]), "+f"((d)[2]), "+f"((d)[3]) \
        : "r"((a)[0]), "r"((a)[1]), "r"((a)[2]), "r"((a)[3]), \
          "r"((b)[0]), "r"((b)[1]))

#define MBAR_INIT(mbar, cnt) \
    asm volatile("mbarrier.init.shared.b64 [%0], %1;" :: "r"(mbar), "r"(cnt) : "memory")
#define MBAR_EXPECT_TX(mbar, bytes) \
    asm volatile("mbarrier.arrive.expect_tx.shared.b64 _, [%0], %1;" \
                 :: "r"(mbar), "r"(bytes) : "memory")
#define MBAR_WAIT(mbar, par) do {                                             \
    uint32_t _m = (mbar), _p = (par), _d;                                     \
    asm volatile("{\n\t.reg .pred p;\n\t"                                     \
        "mbarrier.try_wait.parity.acquire.cta.shared::cta.b64 p, [%1], %2;\n\t"\
        "selp.b32 %0, 1, 0, p;\n\t}" : "=r"(_d) : "r"(_m), "r"(_p) : "memory");\
    if (!_d) {                                                                \
        asm volatile("{\n\t.reg .pred P1;\n\t"                                \
        "WL_%=:\n\t"                                                          \
        "mbarrier.try_wait.parity.acquire.cta.shared::cta.b64 P1, [%0], %1, 0x989680;\n\t"\
        "@P1 bra.uni WD_%=;\n\tbra.uni WL_%=;\n\tWD_%=:\n\t}"                 \
        :: "r"(_m), "r"(_p) : "memory");                                      \
    } } while (0)

#define TMA2D(smemaddr, mapptr, x, y, mbar) \
    asm volatile("cp.async.bulk.tensor.2d.shared::cta.global.tile.mbarrier::complete_tx::bytes " \
                 "[%0], [%1, {%2, %3}], [%4];" \
                 :: "r"(smemaddr), "l"(mapptr), "r"(x), "r"(y), "r"(mbar) : "memory")

// ---------------------------------------------------------------------------
__global__ void reset_kernel() {
    if (threadIdx.x == 0) g_tilectr = 0;
    if (threadIdx.x < NRB) g_ready[threadIdx.x] = 0;
}

// ---------------------------------------------------------------------------
__global__ void alpha_kernel(const float* __restrict__ hs,
                             const int* __restrict__ lengths) {
    int b = blockIdx.x;
    const float* base = hs + (size_t)b * TT * HH + (HH - 1);
    float s = 0.f;
    for (int t = threadIdx.x; t < TT; t += blockDim.x)
        s += 1.f / (1.f + expf(-base[(size_t)t * HH]));
    __shared__ float red[256];
    red[threadIdx.x] = s;
    __syncthreads();
    for (int o = 128; o > 0; o >>= 1) {
        if (threadIdx.x < o) red[threadIdx.x] += red[threadIdx.x + o];
        __syncthreads();
    }
    if (threadIdx.x == 0) {
        float sum = red[0];
        int li = lengths[b];
        float tll = (float)(li < LQ ? li : LQ);
        g_scale[b] = tll / sum;
        float d = tll - sum;
        g_nhat_part[b] = d * d;
    }
}
__global__ void nhat_kernel(float* __restrict__ out) {
    float v = g_nhat_part[threadIdx.x];
    #pragma unroll
    for (int o = 16; o > 0; o >>= 1) v += __shfl_down_sync(0xffffffffu, v, o);
    if (threadIdx.x == 0) out[0] = v;
}

// ---------------------------------------------------------------------------
// Kernel 2: CIF scan -> fp16 plane, 4-deep h prefetch (ILP). Pad lane -> 0.
// ---------------------------------------------------------------------------
__global__ void cif_scan_kernel(const float* __restrict__ hs) {
    int b = blockIdx.y;
    int f = blockIdx.x * blockDim.x + threadIdx.x;
    __shared__ float s_alpha[LQ];
    float scale = g_scale[b];
    const float* hb = hs + (size_t)b * TT * HH;
    for (int t = threadIdx.x; t < LQ; t += blockDim.x)
        s_alpha[t] = scale / (1.f + expf(-hb[(size_t)t * HH + (HH - 1)]));
    __syncthreads();

    bool valid = (f < HM1);
    const float* hcol = hb + f;
    size_t obase = (size_t)b * LQ * HH + f;

    float a_r = 0.f, s_r = 0.f;
    float hbuf[4];
    #pragma unroll
    for (int k = 0; k < 4; ++k)
        hbuf[k] = valid ? hcol[(size_t)k * HH] : 0.f;

    for (int t = 0; t < LQ; t += 4) {
        float hn[4];
        #pragma unroll
        for (int k = 0; k < 4; ++k)        // rows t+4..t+7 <= 403 < 1500
            hn[k] = valid ? hcol[(size_t)(t + 4 + k) * HH] : 0.f;
        #pragma unroll
        for (int k = 0; k < 4; ++k) {
            float a = s_alpha[t + k];
            float h = hbuf[k];
            float a_a = a + a_r;
            float rem = 1.0f - a_r;
            float s_a_nf = s_r + a * h;
            float s_a;
            if (a_a >= 1.0f) {
                float a_r_f = a - rem;
                s_a = s_r + rem * h;
                a_r = a_r_f;
                s_r = a_r_f * h;
            } else {
                a_r = a_a; s_a = s_a_nf; s_r = s_a_nf;
            }
            g_sa[obase + (size_t)(t + k) * HH] = __float2half_rn(s_a);
        }
        #pragma unroll
        for (int k = 0; k < 4; ++k) hbuf[k] = hn[k];
    }
}

// ---------------------------------------------------------------------------
__global__ void wtrans_kernel(const float* __restrict__ W,
                              __half* __restrict__ Wt, int Kvalid) {
    __shared__ float t[32][33];
    int n = blockIdx.x * 32 + threadIdx.x;
    #pragma unroll
    for (int j = 0; j < 32; j += 8) {
        int k = blockIdx.y * 32 + threadIdx.y + j;
        t[threadIdx.y + j][threadIdx.x] = (k < Kvalid) ? W[(size_t)k * HH + n] : 0.f;
    }
    __syncthreads();
    #pragma unroll
    for (int j = 0; j < 32; j += 8) {
        int nn = blockIdx.x * 32 + threadIdx.y + j;
        int kk = blockIdx.y * 32 + threadIdx.x;
        Wt[(size_t)nn * HH + kk] = __float2half_rn(t[threadIdx.x][threadIdx.y + j]);
    }
}

// ---------------------------------------------------------------------------
// Fused persistent GEMM: 296 CTAs (2/SM) x 256 thr, dynamic counter over
// 1200 tiles. NO static shared (the R13 bug: static smem shifted the dynamic
// base and broke TMA's 1024B alignment). sh_t lives in the dynamic header;
// base pinned with __align__(1024).
// ---------------------------------------------------------------------------
#define KCH 64
#define NCHUNK (HH / KCH)            /* 12 */
#define MATB 16384
#define STAGEB 32768
#define NSTAGE 3
#define SOFF 1024
#define SMEM_SZ (SOFF + NSTAGE * STAGEB)   /* 99328 */

__device__ __forceinline__ void issue_chunk(uint32_t sb,
    const CUtensorMap* mA, const CUtensorMap* mB, int c, int row0, int col0) {
    int s = c % NSTAGE;
    uint32_t st = sb + SOFF + s * STAGEB;
    MBAR_EXPECT_TX(sb + s * 8, STAGEB);
    TMA2D(st,        mA, c * KCH, row0, sb + s * 8);
    TMA2D(st + MATB, mB, c * KCH, col0, sb + s * 8);
}

__global__ void __launch_bounds__(256, 2)
gemm_fused(const __grid_constant__ CUtensorMap tmA1,
           const __grid_constant__ CUtensorMap tmB1,
           const __grid_constant__ CUtensorMap tmA2,
           const __grid_constant__ CUtensorMap tmB2,
           const float* __restrict__ b1, const float* __restrict__ b2,
           __half* __restrict__ yout,
           float* __restrict__ outbm, float* __restrict__ fcout,
           const float* __restrict__ bert, const float* __restrict__ mixu) {
    extern __shared__ __align__(1024) char smem[];
    uint32_t sb = smem_u32(smem);
    int* sh_t = (int*)(smem + 32);       // dynamic-header slot (after mbarriers)
    int tid = threadIdx.x, lane = tid & 31, wid = tid >> 5;
    int wr = wid >> 2, wc = wid & 3;

    if (tid == 0) {
        #pragma unroll
        for (int s = 0; s < NSTAGE; ++s) MBAR_INIT(sb + s * 8, 1);
        *sh_t = atomicAdd(&g_tilectr, 1);
    }
    __syncthreads();

    int a_row = lane & 15;
    int a_un  = lane >> 4;
    int b_row = (lane & 7) + ((lane & 16) >> 1);
    int b_un  = (lane & 8) >> 3;
    int tr = lane >> 2;
    int tc = (lane & 3) * 2;

    int tile = *sh_t;
    int preissued = -1;

    while (tile < TILES_ALL) {
        int is1 = (tile < TILES1);
        int u = is1 ? tile : tile - TILES1;
        int rb = u / NCB, cb = u % NCB;
        int row0 = rb * 128, col0 = cb * 128;
        const CUtensorMap* mA = is1 ? &tmA1 : &tmA2;
        const CUtensorMap* mB = is1 ? &tmB1 : &tmB2;

        if (!is1) {
            if (tid == 0)
                while (ld_acquire(&g_ready[rb]) < NCB) __nanosleep(256);
            __syncthreads();
        }
        if (preissued != tile && tid == 0) {
            issue_chunk(sb, mA, mB, 0, row0, col0);
            issue_chunk(sb, mA, mB, 1, row0, col0);
        }

        float acc[4][4][4];
        #pragma unroll
        for (int i = 0; i < 4; ++i)
            #pragma unroll
            for (int j = 0; j < 4; ++j)
                #pragma unroll
                for (int d = 0; d < 4; ++d) acc[i][j][d] = 0.f;

        for (int i = 0; i < NCHUNK; ++i) {
            if (tid == 0 && i + 2 < NCHUNK)
                issue_chunk(sb, mA, mB, i + 2, row0, col0);
            MBAR_WAIT(sb + (i % NSTAGE) * 8, (i / NSTAGE) & 1);

            uint32_t base = sb + SOFF + (i % NSTAGE) * STAGEB;
            #pragma unroll
            for (int kk = 0; kk < KCH; kk += 16) {
                uint32_t ah[4][4], bh[4][2];
                #pragma unroll
                for (int m = 0; m < 4; ++m) {
                    int r = wr * 64 + m * 16 + a_row;
                    int un = (kk >> 3) + a_un;
                    uint32_t off = base + r * 128 + ((un ^ (r & 7)) << 4);
                    LDM4(ah[m], off);
                }
                #pragma unroll
                for (int jp = 0; jp < 2; ++jp) {
                    int r = wc * 32 + jp * 16 + b_row;
                    int un = (kk >> 3) + b_un;
                    uint32_t off = base + MATB + r * 128 + ((un ^ (r & 7)) << 4);
                    uint32_t t0[4];
                    LDM4(t0, off);
                    bh[2*jp][0] = t0[0]; bh[2*jp][1] = t0[1];
                    bh[2*jp+1][0] = t0[2]; bh[2*jp+1][1] = t0[3];
                }
                #pragma unroll
                for (int m = 0; m < 4; ++m)
                    #pragma unroll
                    for (int j = 0; j < 4; ++j)
                        MMAH(acc[m][j], ah[m], bh[j]);
            }
            __syncthreads();
        }

        // claim next tile; pre-issue its prologue ONLY if it is GEMM1
        if (tid == 0) *sh_t = atomicAdd(&g_tilectr, 1);
        __syncthreads();
        int nt = *sh_t;
        preissued = -1;
        if (nt < TILES1) {              // dependency-free: safe to pre-issue
            if (tid == 0) {
                int nu = nt, nrb = nu / NCB, ncb = nu % NCB;
                issue_chunk(sb, &tmA1, &tmB1, 0, nrb * 128, ncb * 128);
                issue_chunk(sb, &tmA1, &tmB1, 1, nrb * 128, ncb * 128);
            }
            preissued = nt;
        }

        // ---- epilogue ----
        const float* bias = is1 ? b1 : b2;
        #pragma unroll
        for (int m = 0; m < 4; ++m) {
            #pragma unroll
            for (int half = 0; half < 2; ++half) {
                int row = row0 + wr * 64 + m * 16 + half * 8 + tr;
                float msk = 0.f;
                if (!is1) msk = (mixu[row] < P_MIX_C) ? 1.f : 0.f;
                #pragma unroll
                for (int j = 0; j < 4; ++j) {
                    int col = col0 + wc * 32 + j * 8 + tc;
                    float v0 = acc[m][j][half * 2 + 0] + bias[col];
                    float v1 = acc[m][j][half * 2 + 1] + bias[col + 1];
                    size_t idx = (size_t)row * HH + col;
                    if (is1) {
                        v0 = fmaxf(v0, 0.f); v1 = fmaxf(v1, 0.f);
                        *(uint32_t*)(yout + idx) =
                            pack2h(__float2half_rn(v0), __float2half_rn(v1));
                    } else {
                        float2 fcv = make_float2(v0, v1);
                        *(float2*)(fcout + idx) = fcv;
                        float2 bm = fcv;
                        if (msk != 0.f) bm = *(const float2*)(bert + idx);
                        *(float2*)(outbm + idx) = bm;
                    }
                }
            }
        }

        if (is1) {                       // publish BEFORE any next-tile spin
            __threadfence();
            __syncthreads();
            if (tid == 0) atomicAdd(&g_ready[rb], 1);
        }
        tile = nt;
    }
}

// ---------------------------------------------------------------------------
typedef CUresult (*TmEncodeFn)(CUtensorMap*, CUtensorMapDataType, cuuint32_t,
                               void*, const cuuint64_t*, const cuuint64_t*,
                               const cuuint32_t*, const cuuint32_t*,
                               CUtensorMapInterleave, CUtensorMapSwizzle,
                               CUtensorMapL2promotion, CUtensorMapFloatOOBfill);

static void encode_map(TmEncodeFn fn, CUtensorMap* m, void* base, cuuint64_t rows) {
    cuuint64_t dims[2]    = {HH, rows};
    cuuint64_t strides[1] = {HH * sizeof(__half)};
    cuuint32_t box[2]     = {KCH, 128};
    cuuint32_t es[2]      = {1, 1};
    fn(m, CU_TENSOR_MAP_DATA_TYPE_FLOAT16, 2, base, dims, strides, box, es,
       CU_TENSOR_MAP_INTERLEAVE_NONE, CU_TENSOR_MAP_SWIZZLE_128B,
       CU_TENSOR_MAP_L2_PROMOTION_L2_128B, CU_TENSOR_MAP_FLOAT_OOB_FILL_NONE);
}

extern "C" void kernel_launch(void* const* d_in, const int* in_sizes, int n_in,
                              void* d_out, int out_size) {
    const float* hs      = (const float*)d_in[0];
    const int*   lengths = (const int*)  d_in[1];
    const float* W1      = (const float*)d_in[2];
    const float* b1      = (const float*)d_in[3];
    const float* W2      = (const float*)d_in[4];
    const float* b2      = (const float*)d_in[5];
    const float* bert    = (const float*)d_in[6];
    const float* mixu    = (const float*)d_in[7];
    float* out = (float*)d_out;

    __half *sa, *y1, *w1t, *w2t;
    cudaGetSymbolAddress((void**)&sa, g_sa);
    cudaGetSymbolAddress((void**)&y1, g_y1);
    cudaGetSymbolAddress((void**)&w1t, g_w1t);
    cudaGetSymbolAddress((void**)&w2t, g_w2t);

    void* fnp = nullptr;
    cudaDriverEntryPointQueryResult qr;
    cudaGetDriverEntryPoint("cuTensorMapEncodeTiled", &fnp,
                            cudaEnableDefault, &qr);
    TmEncodeFn enc = (TmEncodeFn)fnp;
    CUtensorMap tmA1, tmB1, tmA2, tmB2;
    encode_map(enc, &tmA1, sa,  MM);
    encode_map(enc, &tmB1, w1t, HH);
    encode_map(enc, &tmA2, y1,  MM);
    encode_map(enc, &tmB2, w2t, HH);

    cudaFuncSetAttribute(gemm_fused, cudaFuncAttributeMaxDynamicSharedMemorySize, SMEM_SZ);

    reset_kernel<<<1, 128>>>();
    alpha_kernel<<<BB, 256>>>(hs, lengths);
    nhat_kernel<<<1, 32>>>(out + NHAT_OFF);
    wtrans_kernel<<<dim3(24, 24), dim3(32, 8)>>>(W1, w1t, HM1);
    wtrans_kernel<<<dim3(24, 24), dim3(32, 8)>>>(W2, w2t, HH);
    cif_scan_kernel<<<dim3(3, BB), 256>>>(hs);

    gemm_fused<<<NCTA, 256, SMEM_SZ>>>(
        tmA1, tmB1, tmA2, tmB2, b1, b2,
        y1, out /*bert_mixing*/, out + FC_OFF /*fc*/, bert, mixu);
}

// round 15
// speedup vs baseline: 1.3372x; 1.0369x over previous
#include <cuda_runtime.h>
#include <cuda.h>
#include <cuda_fp16.h>
#include <math.h>
#include <stdint.h>

#define BB 32
#define TT 1500
#define HH 768
#define HM1 767
#define LQ 400
#define MM (BB*LQ)                 /* 12800 */
#define FC_OFF ((size_t)MM*HH)
#define NHAT_OFF ((size_t)2*MM*HH)
#define P_MIX_C 0.15f

#define NRB 100
#define NCB 6
#define TILES1 (NRB*NCB)           /* 600 */
#define TILES_ALL (2*TILES1)       /* 1200 */
#define NCTA 296                   /* 148 SMs x 2 CTAs */

/* work-unit map */
#define NU_ALPHA BB                /* 32 */
#define NU_WT    192               /* 2 mats x 24 colblocks x 4 kgroups */
#define NU_SCAN  (3*BB)            /* 96 */
#define U_WT0    NU_ALPHA          /* 32 */
#define U_SCAN0  (U_WT0 + NU_WT)   /* 224 */
#define U_NHAT   (U_SCAN0 + NU_SCAN) /* 320 */
#define U_GEMM0  (U_NHAT + 1)      /* 321 */
#define U_TOTAL  (U_GEMM0 + TILES_ALL) /* 1521 */

// ---------------- scratch (__device__ globals, no allocs) ------------------
__device__ float g_scale[BB];
__device__ float g_nhat_part[BB];
__device__ int   g_tilectr;
__device__ int   g_ready[NRB];
__device__ int   g_wt_ready[2];
__device__ int   g_alpha_ready[BB];
__device__ int   g_scan_ready[BB];
__device__ __half g_sa[(size_t)MM * HH];
__device__ __half g_y1[(size_t)MM * HH];
__device__ __half g_w1t[(size_t)HH * HH];
__device__ __half g_w2t[(size_t)HH * HH];

// ---------------- helpers --------------------------------------------------
__device__ __forceinline__ uint32_t smem_u32(const void* p) {
    uint32_t a;
    asm("{ .reg .u64 t; cvta.to.shared.u64 t, %1; cvt.u32.u64 %0, t; }"
        : "=r"(a) : "l"(p));
    return a;
}
__device__ __forceinline__ uint32_t pack2h(__half a, __half b) {
    return (uint32_t)__half_as_ushort(a) |
           ((uint32_t)__half_as_ushort(b) << 16);
}
__device__ __forceinline__ int ld_acquire(const int* p) {
    int v;
    asm volatile("ld.global.acquire.gpu.b32 %0, [%1];" : "=r"(v) : "l"(p) : "memory");
    return v;
}

#define LDM4(r, addr) \
    asm volatile("ldmatrix.sync.aligned.m8n8.x4.shared.b16 {%0,%1,%2,%3},[%4];" \
        : "=r"((r)[0]), "=r"((r)[1]), "=r"((r)[2]), "=r"((r)[3]) : "r"(addr))

#define MMAH(d, a, b) \
    asm volatile("mma.sync.aligned.m16n8k16.row.col.f32.f16.f16.f32 " \
        "{%0,%1,%2,%3},{%4,%5,%6,%7},{%8,%9},{%0,%1,%2,%3};" \
        : "+f"((d)[0]), "+f"((d)[1]), "+f"((d)[2]), "+f"((d)[3]) \
        : "r"((a)[0]), "r"((a)[1]), "r"((a)[2]), "r"((a)[3]), \
          "r"((b)[0]), "r"((b)[1]))

#define MBAR_INIT(mbar, cnt) \
    asm volatile("mbarrier.init.shared.b64 [%0], %1;" :: "r"(mbar), "r"(cnt) : "memory")
#define MBAR_EXPECT_TX(mbar, bytes) \
    asm volatile("mbarrier.arrive.expect_tx.shared.b64 _, [%0], %1;" \
                 :: "r"(mbar), "r"(bytes) : "memory")
#define MBAR_WAIT(mbar, par) do {                                             \
    uint32_t _m = (mbar), _p = (par), _d;                                     \
    asm volatile("{\n\t.reg .pred p;\n\t"                                     \
        "mbarrier.try_wait.parity.acquire.cta.shared::cta.b64 p, [%1], %2;\n\t"\
        "selp.b32 %0, 1, 0, p;\n\t}" : "=r"(_d) : "r"(_m), "r"(_p) : "memory");\
    if (!_d) {                                                                \
        asm volatile("{\n\t.reg .pred P1;\n\t"                                \
        "WL_%=:\n\t"                                                          \
        "mbarrier.try_wait.parity.acquire.cta.shared::cta.b64 P1, [%0], %1, 0x989680;\n\t"\
        "@P1 bra.uni WD_%=;\n\tbra.uni WL_%=;\n\tWD_%=:\n\t}"                 \
        :: "r"(_m), "r"(_p) : "memory");                                      \
    } } while (0)

#define TMA2D(smemaddr, mapptr, x, y, mbar) \
    asm volatile("cp.async.bulk.tensor.2d.shared::cta.global.tile.mbarrier::complete_tx::bytes " \
                 "[%0], [%1, {%2, %3}], [%4];" \
                 :: "r"(smemaddr), "l"(mapptr), "r"(x), "r"(y), "r"(mbar) : "memory")

// ---------------------------------------------------------------------------
__global__ void reset_kernel() {
    int t = threadIdx.x;
    if (t == 0) g_tilectr = 0;
    if (t < NRB) g_ready[t] = 0;
    if (t < BB) { g_alpha_ready[t] = 0; g_scan_ready[t] = 0; }
    if (t < 2) g_wt_ready[t] = 0;
}

// ---------------------------------------------------------------------------
// Prelude work units (run inside the persistent kernel; noinline keeps their
// register pressure away from the GEMM hot loop).
// ---------------------------------------------------------------------------
__device__ __noinline__ void do_alpha(const float* hs, const int* lengths,
                                      int b, char* smem) {
    float* red = (float*)(smem + 64);
    int tid = threadIdx.x;
    const float* base = hs + (size_t)b * TT * HH + (HH - 1);
    float s = 0.f;
    for (int t = tid; t < TT; t += 256)
        s += 1.f / (1.f + expf(-base[(size_t)t * HH]));
    red[tid] = s;
    __syncthreads();
    for (int o = 128; o > 0; o >>= 1) {
        if (tid < o) red[tid] += red[tid + o];
        __syncthreads();
    }
    if (tid == 0) {
        float sum = red[0];
        int li = lengths[b];
        float tll = (float)(li < LQ ? li : LQ);
        g_scale[b] = tll / sum;
        float d = tll - sum;
        g_nhat_part[b] = d * d;
        __threadfence();
        atomicAdd(&g_alpha_ready[b], 1);
    }
}

__device__ __noinline__ void do_wtrans(const float* W1, const float* W2,
                                       int mat, int cb, int kg, char* smem) {
    const float* W = mat ? W2 : W1;
    int Kvalid = mat ? HH : HM1;
    __half* Wt = mat ? g_w2t : g_w1t;
    float* t = (float*)(smem + 64);      // [32][33]
    int tid = threadIdx.x, tx = tid & 31, ty = tid >> 5;
    for (int kb = kg * 6; kb < kg * 6 + 6; ++kb) {
        #pragma unroll
        for (int j = 0; j < 32; j += 8) {
            int k = kb * 32 + ty + j;
            t[(ty + j) * 33 + tx] = (k < Kvalid) ? W[(size_t)k * HH + cb * 32 + tx] : 0.f;
        }
        __syncthreads();
        #pragma unroll
        for (int j = 0; j < 32; j += 8) {
            int nn = cb * 32 + ty + j;
            int kk = kb * 32 + tx;
            Wt[(size_t)nn * HH + kk] = __float2half_rn(t[tx * 33 + ty + j]);
        }
        __syncthreads();
    }
    __threadfence();
    __syncthreads();
    if (tid == 0) atomicAdd(&g_wt_ready[mat], 1);
}

__device__ __noinline__ void do_scan(const float* hs, int b, int xb, char* smem) {
    float* salpha = (float*)(smem + 64);   // 400 floats
    int tid = threadIdx.x;
    if (tid == 0)
        while (ld_acquire(&g_alpha_ready[b]) < 1) __nanosleep(128);
    __syncthreads();
    float scale = g_scale[b];
    const float* hb = hs + (size_t)b * TT * HH;
    for (int t = tid; t < LQ; t += 256)
        salpha[t] = scale / (1.f + expf(-hb[(size_t)t * HH + (HH - 1)]));
    __syncthreads();

    int f = xb * 256 + tid;               // 0..767
    bool valid = (f < HM1);
    const float* hcol = hb + f;
    size_t obase = (size_t)b * LQ * HH + f;

    float a_r = 0.f, s_r = 0.f;
    float hbuf[4];
    #pragma unroll
    for (int k = 0; k < 4; ++k)
        hbuf[k] = valid ? hcol[(size_t)k * HH] : 0.f;

    for (int t = 0; t < LQ; t += 4) {
        float hn[4];
        #pragma unroll
        for (int k = 0; k < 4; ++k)
            hn[k] = valid ? hcol[(size_t)(t + 4 + k) * HH] : 0.f;
        #pragma unroll
        for (int k = 0; k < 4; ++k) {
            float a = salpha[t + k];
            float h = hbuf[k];
            float a_a = a + a_r;
            float rem = 1.0f - a_r;
            float s_a_nf = s_r + a * h;
            float s_a;
            if (a_a >= 1.0f) {
                float a_r_f = a - rem;
                s_a = s_r + rem * h;
                a_r = a_r_f;
                s_r = a_r_f * h;
            } else {
                a_r = a_a; s_a = s_a_nf; s_r = s_a_nf;
            }
            g_sa[obase + (size_t)(t + k) * HH] = __float2half_rn(s_a);
        }
        #pragma unroll
        for (int k = 0; k < 4; ++k) hbuf[k] = hn[k];
    }
    __threadfence();
    __syncthreads();
    if (tid == 0) atomicAdd(&g_scan_ready[b], 1);
}

__device__ __noinline__ void do_nhat(float* out) {
    if (threadIdx.x == 0) {
        float s = 0.f;
        for (int b = 0; b < BB; ++b) {
            while (ld_acquire(&g_alpha_ready[b]) < 1) __nanosleep(128);
            s += g_nhat_part[b];
        }
        out[NHAT_OFF] = s;
    }
    __syncthreads();
}

// ---------------------------------------------------------------------------
// Mega persistent kernel: prelude units + fused double-GEMM, one launch.
// ---------------------------------------------------------------------------
#define KCH 64
#define NCHUNK (HH / KCH)            /* 12 */
#define MATB 16384
#define STAGEB 32768
#define NSTAGE 3
#define SOFF 1024
#define SMEM_SZ (SOFF + NSTAGE * STAGEB)   /* 99328 */

__device__ __forceinline__ void issue_chunk(uint32_t sb,
    const CUtensorMap* mA, const CUtensorMap* mB, int c, int row0, int col0) {
    int s = c % NSTAGE;
    uint32_t st = sb + SOFF + s * STAGEB;
    MBAR_EXPECT_TX(sb + s * 8, STAGEB);
    TMA2D(st,        mA, c * KCH, row0, sb + s * 8);
    TMA2D(st + MATB, mB, c * KCH, col0, sb + s * 8);
}

__global__ void __launch_bounds__(256, 2)
mega_kernel(const __grid_constant__ CUtensorMap tmA1,
            const __grid_constant__ CUtensorMap tmB1,
            const __grid_constant__ CUtensorMap tmA2,
            const __grid_constant__ CUtensorMap tmB2,
            const float* __restrict__ hs, const int* __restrict__ lengths,
            const float* __restrict__ W1, const float* __restrict__ W2,
            const float* __restrict__ b1, const float* __restrict__ b2,
            float* __restrict__ out,
            const float* __restrict__ bert, const float* __restrict__ mixu) {
    extern __shared__ __align__(1024) char smem[];
    uint32_t sb = smem_u32(smem);
    int* sh_t = (int*)(smem + 32);
    int* sh_flag = (int*)(smem + 36);
    int tid = threadIdx.x, lane = tid & 31, wid = tid >> 5;
    int wr = wid >> 2, wc = wid & 3;

    if (tid == 0) {
        #pragma unroll
        for (int s = 0; s < NSTAGE; ++s) MBAR_INIT(sb + s * 8, 1);
        *sh_t = atomicAdd(&g_tilectr, 1);
    }
    __syncthreads();

    int a_row = lane & 15;
    int a_un  = lane >> 4;
    int b_row = (lane & 7) + ((lane & 16) >> 1);
    int b_un  = (lane & 8) >> 3;
    int tr = lane >> 2;
    int tc = (lane & 3) * 2;

    int unit = *sh_t;
    int preissued = -1;

    while (unit < U_TOTAL) {
        if (unit < U_GEMM0) {
            if (unit < U_WT0) {
                do_alpha(hs, lengths, unit, smem);
            } else if (unit < U_SCAN0) {
                int w = unit - U_WT0;
                do_wtrans(W1, W2, w / 96, (w % 96) >> 2, w & 3, smem);
            } else if (unit < U_NHAT) {
                int s = unit - U_SCAN0;
                do_scan(hs, s / 3, s % 3, smem);
            } else {
                do_nhat(out);
            }
            __syncthreads();
            if (tid == 0) *sh_t = atomicAdd(&g_tilectr, 1);
            __syncthreads();
            unit = *sh_t;
            continue;
        }

        int tile = unit - U_GEMM0;
        int is1 = (tile < TILES1);
        int u = is1 ? tile : tile - TILES1;
        int rb = u / NCB, cb = u % NCB;
        int row0 = rb * 128, col0 = cb * 128;
        const CUtensorMap* mA = is1 ? &tmA1 : &tmA2;
        const CUtensorMap* mB = is1 ? &tmB1 : &tmB2;

        if (preissued != unit) {
            if (tid == 0) {
                if (is1) {
                    while (ld_acquire(&g_wt_ready[0]) < 96) __nanosleep(128);
                    int b0 = row0 / 400, b1e = (row0 + 127) / 400;
                    for (int b = b0; b <= b1e; ++b)
                        while (ld_acquire(&g_scan_ready[b]) < 3) __nanosleep(128);
                } else {
                    while (ld_acquire(&g_wt_ready[1]) < 96) __nanosleep(128);
                    while (ld_acquire(&g_ready[rb]) < NCB) __nanosleep(256);
                }
            }
            __syncthreads();
            if (tid == 0) {
                issue_chunk(sb, mA, mB, 0, row0, col0);
                issue_chunk(sb, mA, mB, 1, row0, col0);
            }
        }

        float acc[4][4][4];
        #pragma unroll
        for (int i = 0; i < 4; ++i)
            #pragma unroll
            for (int j = 0; j < 4; ++j)
                #pragma unroll
                for (int d = 0; d < 4; ++d) acc[i][j][d] = 0.f;

        for (int i = 0; i < NCHUNK; ++i) {
            if (tid == 0 && i + 2 < NCHUNK)
                issue_chunk(sb, mA, mB, i + 2, row0, col0);
            MBAR_WAIT(sb + (i % NSTAGE) * 8, (i / NSTAGE) & 1);

            uint32_t base = sb + SOFF + (i % NSTAGE) * STAGEB;
            #pragma unroll
            for (int kk = 0; kk < KCH; kk += 16) {
                uint32_t ah[4][4], bh[4][2];
                #pragma unroll
                for (int m = 0; m < 4; ++m) {
                    int r = wr * 64 + m * 16 + a_row;
                    int un = (kk >> 3) + a_un;
                    uint32_t off = base + r * 128 + ((un ^ (r & 7)) << 4);
                    LDM4(ah[m], off);
                }
                #pragma unroll
                for (int jp = 0; jp < 2; ++jp) {
                    int r = wc * 32 + jp * 16 + b_row;
                    int un = (kk >> 3) + b_un;
                    uint32_t off = base + MATB + r * 128 + ((un ^ (r & 7)) << 4);
                    uint32_t t0[4];
                    LDM4(t0, off);
                    bh[2*jp][0] = t0[0]; bh[2*jp][1] = t0[1];
                    bh[2*jp+1][0] = t0[2]; bh[2*jp+1][1] = t0[3];
                }
                #pragma unroll
                for (int m = 0; m < 4; ++m)
                    #pragma unroll
                    for (int j = 0; j < 4; ++j)
                        MMAH(acc[m][j], ah[m], bh[j]);
            }
            __syncthreads();
        }

        // claim next unit; pre-issue its prologue if it's a GEMM1 tile whose
        // deps are already satisfied (non-blocking check, smem-broadcast).
        if (tid == 0) *sh_t = atomicAdd(&g_tilectr, 1);
        __syncthreads();
        int ntu = *sh_t;
        if (tid == 0) {
            int ok = 0;
            if (ntu >= U_GEMM0 && ntu < U_GEMM0 + TILES1) {
                int ntile = ntu - U_GEMM0, nrb = ntile / NCB;
                ok = (ld_acquire(&g_wt_ready[0]) >= 96);
                if (ok) {
                    int b0 = (nrb * 128) / 400, b1e = (nrb * 128 + 127) / 400;
                    for (int b = b0; b <= b1e; ++b)
                        if (ld_acquire(&g_scan_ready[b]) < 3) { ok = 0; break; }
                }
            }
            *sh_flag = ok;
        }
        __syncthreads();
        preissued = -1;
        if (*sh_flag) {
            if (tid == 0) {
                int ntile = ntu - U_GEMM0;
                int nrb = ntile / NCB, ncb = ntile % NCB;
                issue_chunk(sb, &tmA1, &tmB1, 0, nrb * 128, ncb * 128);
                issue_chunk(sb, &tmA1, &tmB1, 1, nrb * 128, ncb * 128);
            }
            preissued = ntu;
        }

        // ---- epilogue ----
        const float* bias = is1 ? b1 : b2;
        float* fcout = out + FC_OFF;
        #pragma unroll
        for (int m = 0; m < 4; ++m) {
            #pragma unroll
            for (int half = 0; half < 2; ++half) {
                int row = row0 + wr * 64 + m * 16 + half * 8 + tr;
                float msk = 0.f;
                if (!is1) msk = (mixu[row] < P_MIX_C) ? 1.f : 0.f;
                #pragma unroll
                for (int j = 0; j < 4; ++j) {
                    int col = col0 + wc * 32 + j * 8 + tc;
                    float v0 = acc[m][j][half * 2 + 0] + bias[col];
                    float v1 = acc[m][j][half * 2 + 1] + bias[col + 1];
                    size_t idx = (size_t)row * HH + col;
                    if (is1) {
                        v0 = fmaxf(v0, 0.f); v1 = fmaxf(v1, 0.f);
                        *(uint32_t*)(g_y1 + idx) =
                            pack2h(__float2half_rn(v0), __float2half_rn(v1));
                    } else {
                        float2 fcv = make_float2(v0, v1);
                        *(float2*)(fcout + idx) = fcv;
                        float2 bm = fcv;
                        if (msk != 0.f) bm = *(const float2*)(bert + idx);
                        *(float2*)(out + idx) = bm;
                    }
                }
            }
        }

        if (is1) {                       // publish BEFORE any next-tile spin
            __threadfence();
            __syncthreads();
            if (tid == 0) atomicAdd(&g_ready[rb], 1);
        }
        unit = ntu;
    }
}

// ---------------------------------------------------------------------------
typedef CUresult (*TmEncodeFn)(CUtensorMap*, CUtensorMapDataType, cuuint32_t,
                               void*, const cuuint64_t*, const cuuint64_t*,
                               const cuuint32_t*, const cuuint32_t*,
                               CUtensorMapInterleave, CUtensorMapSwizzle,
                               CUtensorMapL2promotion, CUtensorMapFloatOOBfill);

static void encode_map(TmEncodeFn fn, CUtensorMap* m, void* base, cuuint64_t rows) {
    cuuint64_t dims[2]    = {HH, rows};
    cuuint64_t strides[1] = {HH * sizeof(__half)};
    cuuint32_t box[2]     = {KCH, 128};
    cuuint32_t es[2]      = {1, 1};
    fn(m, CU_TENSOR_MAP_DATA_TYPE_FLOAT16, 2, base, dims, strides, box, es,
       CU_TENSOR_MAP_INTERLEAVE_NONE, CU_TENSOR_MAP_SWIZZLE_128B,
       CU_TENSOR_MAP_L2_PROMOTION_L2_128B, CU_TENSOR_MAP_FLOAT_OOB_FILL_NONE);
}

extern "C" void kernel_launch(void* const* d_in, const int* in_sizes, int n_in,
                              void* d_out, int out_size) {
    const float* hs      = (const float*)d_in[0];
    const int*   lengths = (const int*)  d_in[1];
    const float* W1      = (const float*)d_in[2];
    const float* b1      = (const float*)d_in[3];
    const float* W2      = (const float*)d_in[4];
    const float* b2      = (const float*)d_in[5];
    const float* bert    = (const float*)d_in[6];
    const float* mixu    = (const float*)d_in[7];
    float* out = (float*)d_out;

    __half *sa, *y1, *w1t, *w2t;
    cudaGetSymbolAddress((void**)&sa, g_sa);
    cudaGetSymbolAddress((void**)&y1, g_y1);
    cudaGetSymbolAddress((void**)&w1t, g_w1t);
    cudaGetSymbolAddress((void**)&w2t, g_w2t);

    void* fnp = nullptr;
    cudaDriverEntryPointQueryResult qr;
    cudaGetDriverEntryPoint("cuTensorMapEncodeTiled", &fnp,
                            cudaEnableDefault, &qr);
    TmEncodeFn enc = (TmEncodeFn)fnp;
    CUtensorMap tmA1, tmB1, tmA2, tmB2;
    encode_map(enc, &tmA1, sa,  MM);
    encode_map(enc, &tmB1, w1t, HH);
    encode_map(enc, &tmA2, y1,  MM);
    encode_map(enc, &tmB2, w2t, HH);

    cudaFuncSetAttribute(mega_kernel, cudaFuncAttributeMaxDynamicSharedMemorySize, SMEM_SZ);

    reset_kernel<<<1, 128>>>();
    mega_kernel<<<NCTA, 256, SMEM_SZ>>>(
        tmA1, tmB1, tmA2, tmB2,
        hs, lengths, W1, W2, b1, b2,
        out, bert, mixu);
}

// round 16
// speedup vs baseline: 1.3689x; 1.0237x over previous
#include <cuda_runtime.h>
#include <cuda.h>
#include <cuda_fp16.h>
#include <math.h>
#include <stdint.h>

#define BB 32
#define TT 1500
#define HH 768
#define HM1 767
#define LQ 400
#define MM (BB*LQ)                 /* 12800 */
#define FC_OFF ((size_t)MM*HH)
#define NHAT_OFF ((size_t)2*MM*HH)
#define P_MIX_C 0.15f

#define NRB 100
#define NCB 6
#define TILES1 (NRB*NCB)           /* 600 */
#define TILES_ALL (2*TILES1)       /* 1200 */
#define NCTA 296                   /* 148 SMs x 2 CTAs */

/* work-unit map: alpha -> scan -> wtrans (so the 24 units claimed late are
   W2 transposes, needed only by GEMM2) */
#define NU_ALPHA BB                /* 32 */
#define U_SCAN0  NU_ALPHA          /* 32 */
#define NU_SCAN  (3*BB)            /* 96 */
#define U_WT0    (U_SCAN0 + NU_SCAN)  /* 128 */
#define NU_WT    192
#define U_NHAT   (U_WT0 + NU_WT)   /* 320 */
#define U_GEMM0  (U_NHAT + 1)      /* 321 */
#define U_TOTAL  (U_GEMM0 + TILES_ALL) /* 1521 */

// ---------------- scratch (__device__ globals, no allocs) ------------------
__device__ float g_scale[BB];
__device__ float g_nhat_part[BB];
__device__ int   g_tilectr;
__device__ int   g_ready[NRB];
__device__ int   g_wt_ready[2];
__device__ int   g_alpha_ready[BB];
__device__ int   g_scan_ready[BB];
__device__ __half g_sa[(size_t)MM * HH];
__device__ __half g_y1[(size_t)MM * HH];
__device__ __half g_w1t[(size_t)HH * HH];
__device__ __half g_w2t[(size_t)HH * HH];

// ---------------- helpers --------------------------------------------------
__device__ __forceinline__ uint32_t smem_u32(const void* p) {
    uint32_t a;
    asm("{ .reg .u64 t; cvta.to.shared.u64 t, %1; cvt.u32.u64 %0, t; }"
        : "=r"(a) : "l"(p));
    return a;
}
__device__ __forceinline__ uint32_t pack2h(__half a, __half b) {
    return (uint32_t)__half_as_ushort(a) |
           ((uint32_t)__half_as_ushort(b) << 16);
}
__device__ __forceinline__ int ld_acquire(const int* p) {
    int v;
    asm volatile("ld.global.acquire.gpu.b32 %0, [%1];" : "=r"(v) : "l"(p) : "memory");
    return v;
}

#define LDM4(r, addr) \
    asm volatile("ldmatrix.sync.aligned.m8n8.x4.shared.b16 {%0,%1,%2,%3},[%4];" \
        : "=r"((r)[0]), "=r"((r)[1]), "=r"((r)[2]), "=r"((r)[3]) : "r"(addr))

#define MMAH(d, a, b) \
    asm volatile("mma.sync.aligned.m16n8k16.row.col.f32.f16.f16.f32 " \
        "{%0,%1,%2,%3},{%4,%5,%6,%7},{%8,%9},{%0,%1,%2,%3};" \
        : "+f"((d)[0]), "+f"((d)[1]), "+f"((d)[2]), "+f"((d)[3]) \
        : "r"((a)[0]), "r"((a)[1]), "r"((a)[2]), "r"((a)[3]), \
          "r"((b)[0]), "r"((b)[1]))

#define MBAR_INIT(mbar, cnt) \
    asm volatile("mbarrier.init.shared.b64 [%0], %1;" :: "r"(mbar), "r"(cnt) : "memory")
#define MBAR_EXPECT_TX(mbar, bytes) \
    asm volatile("mbarrier.arrive.expect_tx.shared.b64 _, [%0], %1;" \
                 :: "r"(mbar), "r"(bytes) : "memory")
#define MBAR_WAIT(mbar, par) do {                                             \
    uint32_t _m = (mbar), _p = (par), _d;                                     \
    asm volatile("{\n\t.reg .pred p;\n\t"                                     \
        "mbarrier.try_wait.parity.acquire.cta.shared::cta.b64 p, [%1], %2;\n\t"\
        "selp.b32 %0, 1, 0, p;\n\t}" : "=r"(_d) : "r"(_m), "r"(_p) : "memory");\
    if (!_d) {                                                                \
        asm volatile("{\n\t.reg .pred P1;\n\t"                                \
        "WL_%=:\n\t"                                                          \
        "mbarrier.try_wait.parity.acquire.cta.shared::cta.b64 P1, [%0], %1, 0x989680;\n\t"\
        "@P1 bra.uni WD_%=;\n\tbra.uni WL_%=;\n\tWD_%=:\n\t}"                 \
        :: "r"(_m), "r"(_p) : "memory");                                      \
    } } while (0)

#define TMA2D(smemaddr, mapptr, x, y, mbar) \
    asm volatile("cp.async.bulk.tensor.2d.shared::cta.global.tile.mbarrier::complete_tx::bytes " \
                 "[%0], [%1, {%2, %3}], [%4];" \
                 :: "r"(smemaddr), "l"(mapptr), "r"(x), "r"(y), "r"(mbar) : "memory")

// ---------------------------------------------------------------------------
__global__ void reset_kernel() {
    int t = threadIdx.x;
    if (t == 0) g_tilectr = 0;
    if (t < NRB) g_ready[t] = 0;
    if (t < BB) { g_alpha_ready[t] = 0; g_scan_ready[t] = 0; }
    if (t < 2) g_wt_ready[t] = 0;
}

// ---------------------------------------------------------------------------
// Prelude work units (run inside the persistent kernel; noinline keeps their
// register pressure away from the GEMM hot loop). All publishes use the
// cumulative two-stage release: syncthreads -> tid0 fence+atomicAdd.
// ---------------------------------------------------------------------------
__device__ __noinline__ void do_alpha(const float* hs, const int* lengths,
                                      int b, char* smem) {
    float* red = (float*)(smem + 64);
    int tid = threadIdx.x;
    const float* base = hs + (size_t)b * TT * HH + (HH - 1);
    float s = 0.f;
    for (int t = tid; t < TT; t += 256)
        s += 1.f / (1.f + expf(-base[(size_t)t * HH]));
    red[tid] = s;
    __syncthreads();
    for (int o = 128; o > 0; o >>= 1) {
        if (tid < o) red[tid] += red[tid + o];
        __syncthreads();
    }
    if (tid == 0) {
        float sum = red[0];
        int li = lengths[b];
        float tll = (float)(li < LQ ? li : LQ);
        g_scale[b] = tll / sum;
        float d = tll - sum;
        g_nhat_part[b] = d * d;
        __threadfence();
        atomicAdd(&g_alpha_ready[b], 1);
    }
}

__device__ __noinline__ void do_wtrans(const float* W1, const float* W2,
                                       int mat, int cb, int kg, char* smem) {
    const float* W = mat ? W2 : W1;
    int Kvalid = mat ? HH : HM1;
    __half* Wt = mat ? g_w2t : g_w1t;
    float* t = (float*)(smem + 64);      // [32][33]
    int tid = threadIdx.x, tx = tid & 31, ty = tid >> 5;
    for (int kb = kg * 6; kb < kg * 6 + 6; ++kb) {
        #pragma unroll
        for (int j = 0; j < 32; j += 8) {
            int k = kb * 32 + ty + j;
            t[(ty + j) * 33 + tx] = (k < Kvalid) ? W[(size_t)k * HH + cb * 32 + tx] : 0.f;
        }
        __syncthreads();
        #pragma unroll
        for (int j = 0; j < 32; j += 8) {
            int nn = cb * 32 + ty + j;
            int kk = kb * 32 + tx;
            Wt[(size_t)nn * HH + kk] = __float2half_rn(t[tx * 33 + ty + j]);
        }
        __syncthreads();
    }
    if (tid == 0) { __threadfence(); atomicAdd(&g_wt_ready[mat], 1); }
}

__device__ __noinline__ void do_scan(const float* hs, int b, int xb, char* smem) {
    float* salpha = (float*)(smem + 64);   // 400 floats
    int tid = threadIdx.x;
    if (tid == 0)
        while (ld_acquire(&g_alpha_ready[b]) < 1) __nanosleep(128);
    __syncthreads();
    float scale = g_scale[b];
    const float* hb = hs + (size_t)b * TT * HH;
    for (int t = tid; t < LQ; t += 256)
        salpha[t] = scale / (1.f + expf(-hb[(size_t)t * HH + (HH - 1)]));
    __syncthreads();

    int f = xb * 256 + tid;               // 0..767
    bool valid = (f < HM1);
    const float* hcol = hb + f;
    size_t obase = (size_t)b * LQ * HH + f;

    float a_r = 0.f, s_r = 0.f;
    float hbuf[4];
    #pragma unroll
    for (int k = 0; k < 4; ++k)
        hbuf[k] = valid ? hcol[(size_t)k * HH] : 0.f;

    for (int t = 0; t < LQ; t += 4) {
        float hn[4];
        #pragma unroll
        for (int k = 0; k < 4; ++k)
            hn[k] = valid ? hcol[(size_t)(t + 4 + k) * HH] : 0.f;
        #pragma unroll
        for (int k = 0; k < 4; ++k) {
            float a = salpha[t + k];
            float h = hbuf[k];
            float a_a = a + a_r;
            float rem = 1.0f - a_r;
            float s_a_nf = s_r + a * h;
            float s_a;
            if (a_a >= 1.0f) {
                float a_r_f = a - rem;
                s_a = s_r + rem * h;
                a_r = a_r_f;
                s_r = a_r_f * h;
            } else {
                a_r = a_a; s_a = s_a_nf; s_r = s_a_nf;
            }
            g_sa[obase + (size_t)(t + k) * HH] = __float2half_rn(s_a);
        }
        #pragma unroll
        for (int k = 0; k < 4; ++k) hbuf[k] = hn[k];
    }
    __syncthreads();
    if (tid == 0) { __threadfence(); atomicAdd(&g_scan_ready[b], 1); }
}

__device__ __noinline__ void do_nhat(float* out) {
    if (threadIdx.x == 0) {
        float s = 0.f;
        for (int b = 0; b < BB; ++b) {
            while (ld_acquire(&g_alpha_ready[b]) < 1) __nanosleep(128);
            s += g_nhat_part[b];
        }
        out[NHAT_OFF] = s;
    }
    __syncthreads();
}

// ---------------------------------------------------------------------------
// Mega persistent kernel: prelude units + fused double-GEMM, one launch.
// ---------------------------------------------------------------------------
#define KCH 64
#define NCHUNK (HH / KCH)            /* 12 */
#define MATB 16384
#define STAGEB 32768
#define NSTAGE 3
#define SOFF 1024
#define SMEM_SZ (SOFF + NSTAGE * STAGEB)   /* 99328 */

__device__ __forceinline__ void issue_chunk(uint32_t sb,
    const CUtensorMap* mA, const CUtensorMap* mB, int c, int row0, int col0) {
    int s = c % NSTAGE;
    uint32_t st = sb + SOFF + s * STAGEB;
    MBAR_EXPECT_TX(sb + s * 8, STAGEB);
    TMA2D(st,        mA, c * KCH, row0, sb + s * 8);
    TMA2D(st + MATB, mB, c * KCH, col0, sb + s * 8);
}

__global__ void __launch_bounds__(256, 2)
mega_kernel(const __grid_constant__ CUtensorMap tmA1,
            const __grid_constant__ CUtensorMap tmB1,
            const __grid_constant__ CUtensorMap tmA2,
            const __grid_constant__ CUtensorMap tmB2,
            const float* __restrict__ hs, const int* __restrict__ lengths,
            const float* __restrict__ W1, const float* __restrict__ W2,
            const float* __restrict__ b1, const float* __restrict__ b2,
            float* __restrict__ out,
            const float* __restrict__ bert, const float* __restrict__ mixu) {
    extern __shared__ __align__(1024) char smem[];
    uint32_t sb = smem_u32(smem);
    int* sh_t = (int*)(smem + 32);
    int* sh_flag = (int*)(smem + 36);
    int tid = threadIdx.x, lane = tid & 31, wid = tid >> 5;
    int wr = wid >> 2, wc = wid & 3;

    if (tid == 0) {
        #pragma unroll
        for (int s = 0; s < NSTAGE; ++s) MBAR_INIT(sb + s * 8, 1);
        *sh_t = atomicAdd(&g_tilectr, 1);
    }
    __syncthreads();

    int a_row = lane & 15;
    int a_un  = lane >> 4;
    int b_row = (lane & 7) + ((lane & 16) >> 1);
    int b_un  = (lane & 8) >> 3;
    int tr = lane >> 2;
    int tc = (lane & 3) * 2;

    int unit = *sh_t;
    int preissued = -1;

    while (unit < U_TOTAL) {
        if (unit < U_GEMM0) {
            if (unit < U_SCAN0) {
                do_alpha(hs, lengths, unit, smem);
            } else if (unit < U_WT0) {
                int s = unit - U_SCAN0;
                do_scan(hs, s / 3, s % 3, smem);
            } else if (unit < U_NHAT) {
                int w = unit - U_WT0;
                do_wtrans(W1, W2, w / 96, (w % 96) >> 2, w & 3, smem);
            } else {
                do_nhat(out);
            }
            __syncthreads();
            if (tid == 0) *sh_t = atomicAdd(&g_tilectr, 1);
            __syncthreads();
            unit = *sh_t;
            continue;
        }

        int tile = unit - U_GEMM0;
        int is1 = (tile < TILES1);
        int u = is1 ? tile : tile - TILES1;
        int rb = u / NCB, cb = u % NCB;
        int row0 = rb * 128, col0 = cb * 128;
        const CUtensorMap* mA = is1 ? &tmA1 : &tmA2;
        const CUtensorMap* mB = is1 ? &tmB1 : &tmB2;

        if (preissued != unit) {
            if (tid == 0) {
                if (is1) {
                    while (ld_acquire(&g_wt_ready[0]) < 96) __nanosleep(128);
                    int b0 = row0 / 400, b1e = (row0 + 127) / 400;
                    for (int b = b0; b <= b1e; ++b)
                        while (ld_acquire(&g_scan_ready[b]) < 3) __nanosleep(128);
                } else {
                    while (ld_acquire(&g_wt_ready[1]) < 96) __nanosleep(128);
                    while (ld_acquire(&g_ready[rb]) < NCB) __nanosleep(256);
                }
            }
            __syncthreads();
            if (tid == 0) {
                issue_chunk(sb, mA, mB, 0, row0, col0);
                issue_chunk(sb, mA, mB, 1, row0, col0);
            }
        }

        float acc[4][4][4];
        #pragma unroll
        for (int i = 0; i < 4; ++i)
            #pragma unroll
            for (int j = 0; j < 4; ++j)
                #pragma unroll
                for (int d = 0; d < 4; ++d) acc[i][j][d] = 0.f;

        for (int i = 0; i < NCHUNK; ++i) {
            if (tid == 0 && i + 2 < NCHUNK)
                issue_chunk(sb, mA, mB, i + 2, row0, col0);
            MBAR_WAIT(sb + (i % NSTAGE) * 8, (i / NSTAGE) & 1);

            uint32_t base = sb + SOFF + (i % NSTAGE) * STAGEB;
            #pragma unroll
            for (int kk = 0; kk < KCH; kk += 16) {
                uint32_t ah[4][4], bh[4][2];
                #pragma unroll
                for (int m = 0; m < 4; ++m) {
                    int r = wr * 64 + m * 16 + a_row;
                    int un = (kk >> 3) + a_un;
                    uint32_t off = base + r * 128 + ((un ^ (r & 7)) << 4);
                    LDM4(ah[m], off);
                }
                #pragma unroll
                for (int jp = 0; jp < 2; ++jp) {
                    int r = wc * 32 + jp * 16 + b_row;
                    int un = (kk >> 3) + b_un;
                    uint32_t off = base + MATB + r * 128 + ((un ^ (r & 7)) << 4);
                    uint32_t t0[4];
                    LDM4(t0, off);
                    bh[2*jp][0] = t0[0]; bh[2*jp][1] = t0[1];
                    bh[2*jp+1][0] = t0[2]; bh[2*jp+1][1] = t0[3];
                }
                #pragma unroll
                for (int m = 0; m < 4; ++m)
                    #pragma unroll
                    for (int j = 0; j < 4; ++j)
                        MMAH(acc[m][j], ah[m], bh[j]);
            }
            __syncthreads();
        }

        // claim next unit; pre-issue its prologue if it's a GEMM1 tile whose
        // deps are already satisfied (non-blocking check, smem-broadcast).
        if (tid == 0) *sh_t = atomicAdd(&g_tilectr, 1);
        __syncthreads();
        int ntu = *sh_t;
        if (tid == 0) {
            int ok = 0;
            if (ntu >= U_GEMM0 && ntu < U_GEMM0 + TILES1) {
                int ntile = ntu - U_GEMM0, nrb = ntile / NCB;
                ok = (ld_acquire(&g_wt_ready[0]) >= 96);
                if (ok) {
                    int b0 = (nrb * 128) / 400, b1e = (nrb * 128 + 127) / 400;
                    for (int b = b0; b <= b1e; ++b)
                        if (ld_acquire(&g_scan_ready[b]) < 3) { ok = 0; break; }
                }
            }
            *sh_flag = ok;
        }
        __syncthreads();
        preissued = -1;
        if (*sh_flag) {
            if (tid == 0) {
                int ntile = ntu - U_GEMM0;
                int nrb = ntile / NCB, ncb = ntile % NCB;
                issue_chunk(sb, &tmA1, &tmB1, 0, nrb * 128, ncb * 128);
                issue_chunk(sb, &tmA1, &tmB1, 1, nrb * 128, ncb * 128);
            }
            preissued = ntu;
        }

        // ---- epilogue ----
        const float* bias = is1 ? b1 : b2;
        float* fcout = out + FC_OFF;
        #pragma unroll
        for (int m = 0; m < 4; ++m) {
            #pragma unroll
            for (int half = 0; half < 2; ++half) {
                int row = row0 + wr * 64 + m * 16 + half * 8 + tr;
                float msk = 0.f;
                if (!is1) msk = (mixu[row] < P_MIX_C) ? 1.f : 0.f;
                #pragma unroll
                for (int j = 0; j < 4; ++j) {
                    int col = col0 + wc * 32 + j * 8 + tc;
                    float v0 = acc[m][j][half * 2 + 0] + bias[col];
                    float v1 = acc[m][j][half * 2 + 1] + bias[col + 1];
                    size_t idx = (size_t)row * HH + col;
                    if (is1) {
                        v0 = fmaxf(v0, 0.f); v1 = fmaxf(v1, 0.f);
                        *(uint32_t*)(g_y1 + idx) =
                            pack2h(__float2half_rn(v0), __float2half_rn(v1));
                    } else {
                        float2 fcv = make_float2(v0, v1);
                        *(float2*)(fcout + idx) = fcv;
                        float2 bm = fcv;
                        if (msk != 0.f) bm = *(const float2*)(bert + idx);
                        *(float2*)(out + idx) = bm;
                    }
                }
            }
        }

        if (is1) {                       // cumulative release: sync -> tid0 fence+add
            __syncthreads();
            if (tid == 0) { __threadfence(); atomicAdd(&g_ready[rb], 1); }
        }
        unit = ntu;
    }
}

// ---------------------------------------------------------------------------
typedef CUresult (*TmEncodeFn)(CUtensorMap*, CUtensorMapDataType, cuuint32_t,
                               void*, const cuuint64_t*, const cuuint64_t*,
                               const cuuint32_t*, const cuuint32_t*,
                               CUtensorMapInterleave, CUtensorMapSwizzle,
                               CUtensorMapL2promotion, CUtensorMapFloatOOBfill);

static void encode_map(TmEncodeFn fn, CUtensorMap* m, void* base, cuuint64_t rows) {
    cuuint64_t dims[2]    = {HH, rows};
    cuuint64_t strides[1] = {HH * sizeof(__half)};
    cuuint32_t box[2]     = {KCH, 128};
    cuuint32_t es[2]      = {1, 1};
    fn(m, CU_TENSOR_MAP_DATA_TYPE_FLOAT16, 2, base, dims, strides, box, es,
       CU_TENSOR_MAP_INTERLEAVE_NONE, CU_TENSOR_MAP_SWIZZLE_128B,
       CU_TENSOR_MAP_L2_PROMOTION_L2_128B, CU_TENSOR_MAP_FLOAT_OOB_FILL_NONE);
}

extern "C" void kernel_launch(void* const* d_in, const int* in_sizes, int n_in,
                              void* d_out, int out_size) {
    const float* hs      = (const float*)d_in[0];
    const int*   lengths = (const int*)  d_in[1];
    const float* W1      = (const float*)d_in[2];
    const float* b1      = (const float*)d_in[3];
    const float* W2      = (const float*)d_in[4];
    const float* b2      = (const float*)d_in[5];
    const float* bert    = (const float*)d_in[6];
    const float* mixu    = (const float*)d_in[7];
    float* out = (float*)d_out;

    __half *sa, *y1, *w1t, *w2t;
    cudaGetSymbolAddress((void**)&sa, g_sa);
    cudaGetSymbolAddress((void**)&y1, g_y1);
    cudaGetSymbolAddress((void**)&w1t, g_w1t);
    cudaGetSymbolAddress((void**)&w2t, g_w2t);

    void* fnp = nullptr;
    cudaDriverEntryPointQueryResult qr;
    cudaGetDriverEntryPoint("cuTensorMapEncodeTiled", &fnp,
                            cudaEnableDefault, &qr);
    TmEncodeFn enc = (TmEncodeFn)fnp;
    CUtensorMap tmA1, tmB1, tmA2, tmB2;
    encode_map(enc, &tmA1, sa,  MM);
    encode_map(enc, &tmB1, w1t, HH);
    encode_map(enc, &tmA2, y1,  MM);
    encode_map(enc, &tmB2, w2t, HH);

    cudaFuncSetAttribute(mega_kernel, cudaFuncAttributeMaxDynamicSharedMemorySize, SMEM_SZ);

    reset_kernel<<<1, 128>>>();
    mega_kernel<<<NCTA, 256, SMEM_SZ>>>(
        tmA1, tmB1, tmA2, tmB2,
        hs, lengths, W1, W2, b1, b2,
        out, bert, mixu);
}